// round 1
// baseline (speedup 1.0000x reference)
#include <cuda_runtime.h>
#include <cstdint>

typedef unsigned long long ull;

#define B 8
#define H 512
#define W 512
#define TS 32
#define NTHREADS 256

// ---------------- device scratch (allocation-free) ----------------
__device__ float g_edges[B * H * W];
__device__ float g_c0[B * H * W * 8];
__device__ float g_c1[B * H * W * 8];
__device__ float g_kpre[B * H * W];
__device__ float g_k2s[72];

// ---------------- f32x2 packed helpers (sm_100+) ----------------
__device__ __forceinline__ ull pack2(float lo, float hi) {
    ull r;
    asm("mov.b64 %0, {%1, %2};" : "=l"(r) : "f"(lo), "f"(hi));
    return r;
}
__device__ __forceinline__ float2 unpack2(ull v) {
    float2 r;
    asm("mov.b64 {%0, %1}, %2;" : "=f"(r.x), "=f"(r.y) : "l"(v));
    return r;
}
__device__ __forceinline__ void fma2(ull& acc, ull a, ull b) {
    asm("fma.rn.f32x2 %0, %1, %2, %0;" : "+l"(acc) : "l"(a), "l"(b));
}

// ---------------- kernel 0: sum curve_2 over its 16 out channels ----------------
// k2 layout HWIO (3,3,8,16): [(t*8+ci)*16 + co]; result [t*8+ci]
__global__ void k_sumk2(const float* __restrict__ k2) {
    int i = threadIdx.x;
    if (i < 72) {
        float s = 0.f;
#pragma unroll
        for (int o = 0; o < 16; ++o) s += k2[i * 16 + o];
        g_k2s[i] = s;
    }
}

// ---------------- kernel 1: edges = softsign(sum(relu(pw(dw(image))))) ----------------
__global__ void k_edges(const float* __restrict__ image,
                        const float* __restrict__ dw,   // (3,3,1,8) -> [t*8+c]
                        const float* __restrict__ pw) { // (1,1,8,8) -> [ci*8+co]
    __shared__ __align__(16) float s_img[34 * 34];
    __shared__ float s_dw[72];
    __shared__ float s_pw[64];

    const int b = blockIdx.z;
    const int x0 = blockIdx.x * TS, y0 = blockIdx.y * TS;
    const int tid = threadIdx.x;

    for (int i = tid; i < 72; i += NTHREADS) s_dw[i] = dw[i];
    for (int i = tid; i < 64; i += NTHREADS) s_pw[i] = pw[i];
    for (int i = tid; i < 34 * 34; i += NTHREADS) {
        int r = i / 34, c = i % 34;
        int gy = y0 - 1 + r, gx = x0 - 1 + c;
        float v = 0.f;
        if (gy >= 0 && gy < H && gx >= 0 && gx < W)
            v = image[((b * H) + gy) * W + gx];
        s_img[i] = v;
    }
    __syncthreads();

    const int tx = tid & 31, ty = tid >> 5;
#pragma unroll
    for (int k = 0; k < 4; ++k) {
        const int py = ty + 8 * k;
        float e1[8];
#pragma unroll
        for (int c = 0; c < 8; ++c) e1[c] = 0.f;
#pragma unroll
        for (int t = 0; t < 9; ++t) {
            int dy = t / 3, dx = t % 3;
            float v = s_img[(py + dy) * 34 + tx + dx];
#pragma unroll
            for (int c = 0; c < 8; ++c) e1[c] = fmaf(v, s_dw[t * 8 + c], e1[c]);
        }
        float s = 0.f;
#pragma unroll
        for (int co = 0; co < 8; ++co) {
            float e2 = 0.f;
#pragma unroll
            for (int ci = 0; ci < 8; ++ci) e2 = fmaf(e1[ci], s_pw[ci * 8 + co], e2);
            s += fmaxf(e2, 0.f);
        }
        float ed = s / (1.f + fabsf(s));
        g_edges[((b * H) + (y0 + py)) * W + (x0 + tx)] = ed;
    }
}

// ---------------- kernel 2: c0 = conv5x5 1->8 of u ----------------
__global__ void k_c0(const float* __restrict__ u,
                     const float* __restrict__ k0) { // (5,5,1,8) -> [t*8+c]
    __shared__ __align__(16) float s_u[36 * 36];
    __shared__ float s_w[200];

    const int b = blockIdx.z;
    const int x0 = blockIdx.x * TS, y0 = blockIdx.y * TS;
    const int tid = threadIdx.x;

    for (int i = tid; i < 200; i += NTHREADS) s_w[i] = k0[i];
    for (int i = tid; i < 36 * 36; i += NTHREADS) {
        int r = i / 36, c = i % 36;
        int gy = y0 - 2 + r, gx = x0 - 2 + c;
        float v = 0.f;
        if (gy >= 0 && gy < H && gx >= 0 && gx < W)
            v = u[((b * H) + gy) * W + gx];
        s_u[i] = v;
    }
    __syncthreads();

    const int tx = tid & 31, ty = tid >> 5;
#pragma unroll
    for (int k = 0; k < 4; ++k) {
        const int py = ty + 8 * k;
        float acc[8];
#pragma unroll
        for (int c = 0; c < 8; ++c) acc[c] = 0.f;
#pragma unroll
        for (int t = 0; t < 25; ++t) {
            int dy = t / 5, dx = t % 5;
            float v = s_u[(py + dy) * 36 + tx + dx];
#pragma unroll
            for (int c = 0; c < 8; ++c) acc[c] = fmaf(v, s_w[t * 8 + c], acc[c]);
        }
        float* dst = g_c0 + (((b * H) + (y0 + py)) * W + (x0 + tx)) * 8;
        float4 o0 = make_float4(acc[0], acc[1], acc[2], acc[3]);
        float4 o1 = make_float4(acc[4], acc[5], acc[6], acc[7]);
        ((float4*)dst)[0] = o0;
        ((float4*)dst)[1] = o1;
    }
}

// ---------------- kernel 3 (dominant): c1 = conv5x5 8->8 of c0, f32x2 packed ----------------
__global__ void k_c1(const float* __restrict__ k1) { // (5,5,8,8) -> [(t*8+ci)*8+co]
    __shared__ __align__(16) float s_t[36 * 36 * 8]; // 41472 B
    __shared__ __align__(16) float s_w[1600];        // 6400 B

    const int b = blockIdx.z;
    const int x0 = blockIdx.x * TS, y0 = blockIdx.y * TS;
    const int tid = threadIdx.x;

    for (int i = tid; i < 1600; i += NTHREADS) s_w[i] = k1[i];
    for (int i = tid; i < 36 * 36; i += NTHREADS) {
        int r = i / 36, c = i % 36;
        int gy = y0 - 2 + r, gx = x0 - 2 + c;
        float4 a = make_float4(0.f, 0.f, 0.f, 0.f);
        float4 bb = make_float4(0.f, 0.f, 0.f, 0.f);
        if (gy >= 0 && gy < H && gx >= 0 && gx < W) {
            const float4* p = (const float4*)(g_c0 + (((b * H) + gy) * W + gx) * 8);
            a = p[0];
            bb = p[1];
        }
        ((float4*)s_t)[i * 2] = a;
        ((float4*)s_t)[i * 2 + 1] = bb;
    }
    __syncthreads();

    const int tx = tid & 31, ty = tid >> 5;
    // acc[px][coPair]: lanes = (co=2j, co=2j+1)
    ull acc[4][4];
#pragma unroll
    for (int p = 0; p < 4; ++p)
#pragma unroll
        for (int j = 0; j < 4; ++j) acc[p][j] = 0ull;

#pragma unroll 1
    for (int ky = 0; ky < 5; ++ky) {
#pragma unroll
        for (int kx = 0; kx < 5; ++kx) {
            const float* wp = s_w + (ky * 5 + kx) * 64;
            const float* t0 = s_t + (((ty + ky) * 36) + (tx + kx)) * 8;
#pragma unroll
            for (int ci = 0; ci < 8; ++ci) {
                ulonglong2 wA = *(const ulonglong2*)(wp + ci * 8);
                ulonglong2 wB = *(const ulonglong2*)(wp + ci * 8 + 4);
                float v0 = t0[ci];
                float v1 = t0[8 * 36 * 8 + ci];
                float v2 = t0[16 * 36 * 8 + ci];
                float v3 = t0[24 * 36 * 8 + ci];
                ull p;
                p = pack2(v0, v0);
                fma2(acc[0][0], p, wA.x); fma2(acc[0][1], p, wA.y);
                fma2(acc[0][2], p, wB.x); fma2(acc[0][3], p, wB.y);
                p = pack2(v1, v1);
                fma2(acc[1][0], p, wA.x); fma2(acc[1][1], p, wA.y);
                fma2(acc[1][2], p, wB.x); fma2(acc[1][3], p, wB.y);
                p = pack2(v2, v2);
                fma2(acc[2][0], p, wA.x); fma2(acc[2][1], p, wA.y);
                fma2(acc[2][2], p, wB.x); fma2(acc[2][3], p, wB.y);
                p = pack2(v3, v3);
                fma2(acc[3][0], p, wA.x); fma2(acc[3][1], p, wA.y);
                fma2(acc[3][2], p, wB.x); fma2(acc[3][3], p, wB.y);
            }
        }
    }

#pragma unroll
    for (int k = 0; k < 4; ++k) {
        int y = y0 + ty + 8 * k;
        float2 a0 = unpack2(acc[k][0]);
        float2 a1 = unpack2(acc[k][1]);
        float2 a2 = unpack2(acc[k][2]);
        float2 a3 = unpack2(acc[k][3]);
        float* dst = g_c1 + (((b * H) + y) * W + (x0 + tx)) * 8;
        ((float4*)dst)[0] = make_float4(a0.x, a0.y, a1.x, a1.y);
        ((float4*)dst)[1] = make_float4(a2.x, a2.y, a3.x, a3.y);
    }
}

// ---------------- kernel 4: kpre = (conv3x3 8->1 with summed k2) * kappa_kernel ----------------
__global__ void k_c2k(const float* __restrict__ kap) { // (H,W,1)
    __shared__ __align__(16) float s_t[34 * 34 * 8]; // 36992 B
    __shared__ float s_k[72];

    const int b = blockIdx.z;
    const int x0 = blockIdx.x * TS, y0 = blockIdx.y * TS;
    const int tid = threadIdx.x;

    for (int i = tid; i < 72; i += NTHREADS) s_k[i] = g_k2s[i];
    for (int i = tid; i < 34 * 34; i += NTHREADS) {
        int r = i / 34, c = i % 34;
        int gy = y0 - 1 + r, gx = x0 - 1 + c;
        float4 a = make_float4(0.f, 0.f, 0.f, 0.f);
        float4 bb = make_float4(0.f, 0.f, 0.f, 0.f);
        if (gy >= 0 && gy < H && gx >= 0 && gx < W) {
            const float4* p = (const float4*)(g_c1 + (((b * H) + gy) * W + gx) * 8);
            a = p[0];
            bb = p[1];
        }
        ((float4*)s_t)[i * 2] = a;
        ((float4*)s_t)[i * 2 + 1] = bb;
    }
    __syncthreads();

    const int tx = tid & 31, ty = tid >> 5;
#pragma unroll
    for (int k = 0; k < 4; ++k) {
        const int py = ty + 8 * k;
        float acc = 0.f;
#pragma unroll
        for (int t = 0; t < 9; ++t) {
            int dy = t / 3, dx = t % 3;
            const float* p = s_t + (((py + dy) * 34) + (tx + dx)) * 8;
#pragma unroll
            for (int ci = 0; ci < 8; ++ci) acc = fmaf(p[ci], s_k[t * 8 + ci], acc);
        }
        int y = y0 + py, x = x0 + tx;
        g_kpre[((b * H) + y) * W + x] = acc * kap[y * W + x];
    }
}

// ---------------- kernel 5: final fuse: grads (3x3x32 relu-sum, f32x2), diffs, smoother, sum ----------------
__global__ void k_final(const float* __restrict__ u,
                        const float* __restrict__ wx, // (3,3,1,32) -> [t*32+co]
                        const float* __restrict__ wy,
                        const float* __restrict__ ws, // (5,5,1,1) -> [t]
                        float* __restrict__ out) {
    __shared__ __align__(16) float s_kp[36 * 36];
    __shared__ __align__(16) float s_e[34 * 34];
    __shared__ __align__(16) float s_u[34 * 34];
    __shared__ __align__(16) float s_wx[288];
    __shared__ __align__(16) float s_wy[288];
    __shared__ float s_ws[25];

    const int b = blockIdx.z;
    const int x0 = blockIdx.x * TS, y0 = blockIdx.y * TS;
    const int tid = threadIdx.x;

    for (int i = tid; i < 288; i += NTHREADS) { s_wx[i] = wx[i]; s_wy[i] = wy[i]; }
    for (int i = tid; i < 25; i += NTHREADS) s_ws[i] = ws[i];
    for (int i = tid; i < 36 * 36; i += NTHREADS) {
        int r = i / 36, c = i % 36;
        int gy = y0 - 2 + r, gx = x0 - 2 + c;
        float v = 0.f;
        if (gy >= 0 && gy < H && gx >= 0 && gx < W)
            v = g_kpre[((b * H) + gy) * W + gx];
        s_kp[i] = v;
    }
    for (int i = tid; i < 34 * 34; i += NTHREADS) {
        int r = i / 34, c = i % 34;
        int gy = y0 - 1 + r, gx = x0 - 1 + c;
        float ve = 0.f, vu = 0.f;
        if (gy >= 0 && gy < H && gx >= 0 && gx < W) {
            int idx = ((b * H) + gy) * W + gx;
            ve = g_edges[idx];
            vu = u[idx];
        }
        s_e[i] = ve;
        s_u[i] = vu;
    }
    __syncthreads();

    const int tx = tid & 31, ty = tid >> 5;
#pragma unroll 1
    for (int k = 0; k < 4; ++k) {
        const int py = ty + 8 * k;

        // splat edge taps once
        ull ev2[9];
#pragma unroll
        for (int t = 0; t < 9; ++t) {
            float v = s_e[(py + t / 3) * 34 + tx + (t % 3)];
            ev2[t] = pack2(v, v);
        }

        float gx = 0.f, gy = 0.f;
#pragma unroll
        for (int j = 0; j < 16; ++j) {
            ull ax = 0ull, ay = 0ull;
#pragma unroll
            for (int t = 0; t < 9; ++t) {
                fma2(ax, ev2[t], *(const ull*)(s_wx + t * 32 + 2 * j));
                fma2(ay, ev2[t], *(const ull*)(s_wy + t * 32 + 2 * j));
            }
            float2 rx = unpack2(ax);
            float2 ry = unpack2(ay);
            gx += fmaxf(rx.x, 0.f) + fmaxf(rx.y, 0.f);
            gy += fmaxf(ry.x, 0.f) + fmaxf(ry.y, 0.f);
        }

        // finite differences (zero padding handled by tile zeros)
        const int ec = (py + 1) * 34 + tx + 1;
        float uc = s_u[ec];
        float xp = uc - s_u[ec - 1];       // u[x] - u[x-1]
        float xn = s_u[ec + 1] - uc;       // u[x+1] - u[x]
        float yn = s_u[ec - 34] - uc;      // u[y-1] - u[y]
        float yp = uc - s_u[ec + 34];      // u[y] - u[y+1]

        // smoother conv on kpre
        float kp = 0.f;
#pragma unroll
        for (int t = 0; t < 25; ++t)
            kp = fmaf(s_kp[(py + t / 5) * 36 + tx + (t % 5)], s_ws[t], kp);

        float fxp = fmaxf(gx, 0.f), fxn = fminf(gx, 0.f);
        float fyp = fmaxf(gy, 0.f), fyn = fminf(gy, 0.f);

        float r = uc + fxp * xp + fxn * xn + fyp * yp + fyn * yn + s_e[ec] + kp;
        out[((b * H) + (y0 + py)) * W + (x0 + tx)] = r;
    }
}

// ---------------- launch ----------------
extern "C" void kernel_launch(void* const* d_in, const int* in_sizes, int n_in,
                              void* d_out, int out_size) {
    (void)in_sizes; (void)n_in; (void)out_size;
    const float* u     = (const float*)d_in[0];
    const float* image = (const float*)d_in[1];
    const float* wx    = (const float*)d_in[2];
    const float* wy    = (const float*)d_in[3];
    const float* dw    = (const float*)d_in[4];
    const float* pw    = (const float*)d_in[5];
    const float* k0    = (const float*)d_in[6];
    const float* k1    = (const float*)d_in[7];
    const float* k2    = (const float*)d_in[8];
    const float* ws    = (const float*)d_in[9];
    const float* kap   = (const float*)d_in[10];
    float* out = (float*)d_out;

    dim3 grid(W / TS, H / TS, B);
    dim3 blk(NTHREADS);

    k_sumk2<<<1, 128>>>(k2);
    k_edges<<<grid, blk>>>(image, dw, pw);
    k_c0<<<grid, blk>>>(u, k0);
    k_c1<<<grid, blk>>>(k1);
    k_c2k<<<grid, blk>>>(kap);
    k_final<<<grid, blk>>>(u, wx, wy, ws, out);
}

// round 3
// speedup vs baseline: 2.6286x; 2.6286x over previous
#include <cuda_runtime.h>
#include <cstdint>

typedef unsigned long long ull;

#define B 8
#define H 512
#define W 512
#define TS 32
#define NTHREADS 256

// ---------------- device scratch (allocation-free) ----------------
__device__ float g_c0[B * H * W * 8];
__device__ float g_c1[B * H * W * 8];
__device__ float g_kpre[B * H * W];
__device__ float g_k2s[72];
__device__ float g_kc[121];

// ---------------- f32x2 packed helpers (sm_100+) ----------------
__device__ __forceinline__ ull pack2(float lo, float hi) {
    ull r;
    asm("mov.b64 %0, {%1, %2};" : "=l"(r) : "f"(lo), "f"(hi));
    return r;
}
__device__ __forceinline__ float2 unpack2(ull v) {
    float2 r;
    asm("mov.b64 {%0, %1}, %2;" : "=f"(r.x), "=f"(r.y) : "l"(v));
    return r;
}
__device__ __forceinline__ void fma2(ull& acc, ull a, ull b) {
    asm("fma.rn.f32x2 %0, %1, %2, %0;" : "+l"(acc) : "l"(a), "l"(b));
}

// ---------------- ring tile mapping (60 border tiles of a 16x16 tile grid) ----------------
__device__ __forceinline__ void ring_tile(int id, int& bx, int& by) {
    if (id < 16)      { bx = id;      by = 0;       }
    else if (id < 32) { bx = id - 16; by = 15;      }
    else if (id < 46) { bx = 0;       by = id - 31; }  // by = 1..14
    else              { bx = 15;      by = id - 45; }  // by = 1..14
}

// ---------------- kernel: compose k0(5x5,1->8) o k1(5x5,8->8) o sum16(k2)(3x3,8->1) -> 11x11 ----------------
__global__ void k_compose(const float* __restrict__ k0,
                          const float* __restrict__ k1,
                          const float* __restrict__ k2) {
    __shared__ float s_k2s[72];
    __shared__ float s_K01[648]; // [ry(9)][rx(9)][c2(8)]
    const int tid = threadIdx.x;

    if (tid < 72) {
        float s = 0.f;
#pragma unroll
        for (int o = 0; o < 16; ++o) s += k2[tid * 16 + o];
        s_k2s[tid] = s;
        g_k2s[tid] = s;
    }
    __syncthreads();

    if (tid < 648) {
        int c2 = tid & 7;
        int rx = (tid >> 3) % 9;
        int ry = tid / 72;
        float v = 0.f;
        int sy0 = ry - 4 > 0 ? ry - 4 : 0, sy1 = ry < 4 ? ry : 4;
        int sx0 = rx - 4 > 0 ? rx - 4 : 0, sx1 = rx < 4 ? rx : 4;
        for (int sy = sy0; sy <= sy1; ++sy)
            for (int sx = sx0; sx <= sx1; ++sx) {
                int ty = ry - sy, txx = rx - sx;
                for (int c1 = 0; c1 < 8; ++c1)
                    v += k0[(sy * 5 + sx) * 8 + c1] *
                         k1[((ty * 5 + txx) * 8 + c1) * 8 + c2];
            }
        s_K01[(ry * 9 + rx) * 8 + c2] = v;
    }
    __syncthreads();

    if (tid < 121) {
        int fx = tid % 11, fy = tid / 11;
        float v = 0.f;
        int ry0 = fy - 2 > 0 ? fy - 2 : 0, ry1 = fy < 8 ? fy : 8;
        int rx0 = fx - 2 > 0 ? fx - 2 : 0, rx1 = fx < 8 ? fx : 8;
        for (int ry = ry0; ry <= ry1; ++ry)
            for (int rx = rx0; rx <= rx1; ++rx) {
                int vy = fy - ry, vx = fx - rx;
                for (int c2 = 0; c2 < 8; ++c2)
                    v += s_K01[(ry * 9 + rx) * 8 + c2] *
                         s_k2s[(vy * 3 + vx) * 8 + c2];
            }
        g_kc[tid] = v;
    }
}

// ---------------- kernel: kpre = conv11x11(u, g_kc) * kappa_kernel  (interior-exact) ----------------
__global__ void k_kpre(const float* __restrict__ u, const float* __restrict__ kap) {
    __shared__ __align__(16) float s_t[42 * 42];
    __shared__ __align__(16) ull   s_t2[34 * 42];
    __shared__ __align__(16) ull   s_K2[121];

    const int b = blockIdx.z;
    const int x0 = blockIdx.x * TS, y0 = blockIdx.y * TS;
    const int tid = threadIdx.x;

    for (int i = tid; i < 121; i += NTHREADS) {
        float w = g_kc[i];
        s_K2[i] = pack2(w, w);
    }
    for (int i = tid; i < 42 * 42; i += NTHREADS) {
        int r = i / 42, c = i % 42;
        int gy = y0 - 5 + r, gx = x0 - 5 + c;
        float v = 0.f;
        if (gy >= 0 && gy < H && gx >= 0 && gx < W)
            v = u[((b * H) + gy) * W + gx];
        s_t[i] = v;
    }
    __syncthreads();
    for (int i = tid; i < 34 * 42; i += NTHREADS)
        s_t2[i] = pack2(s_t[i], s_t[i + 8 * 42]);
    __syncthreads();

    const int tx = tid & 31, ty = tid >> 5;
#pragma unroll
    for (int pair = 0; pair < 2; ++pair) {
        ull acc = 0ull;
        const int base = ty + 16 * pair;
#pragma unroll 1
        for (int dy = 0; dy < 11; ++dy) {
            const ull* tp = s_t2 + (base + dy) * 42 + tx;
            const ull* wp = s_K2 + dy * 11;
#pragma unroll
            for (int dx = 0; dx < 11; ++dx) fma2(acc, tp[dx], wp[dx]);
        }
        float2 r = unpack2(acc);
        int y = y0 + ty + 16 * pair;
        int x = x0 + tx;
        g_kpre[((b * H) + y) * W + x]       = r.x * kap[y * W + x];
        g_kpre[((b * H) + y + 8) * W + x]   = r.y * kap[(y + 8) * W + x];
    }
}

// ---------------- ring kernel: c0 = conv5x5 1->8 of u (border tiles only) ----------------
__global__ void k_c0(const float* __restrict__ u,
                     const float* __restrict__ k0) {
    __shared__ __align__(16) float s_u[36 * 36];
    __shared__ float s_w[200];

    const int b = blockIdx.y;
    int bx, by; ring_tile(blockIdx.x, bx, by);
    const int x0 = bx * TS, y0 = by * TS;
    const int tid = threadIdx.x;

    for (int i = tid; i < 200; i += NTHREADS) s_w[i] = k0[i];
    for (int i = tid; i < 36 * 36; i += NTHREADS) {
        int r = i / 36, c = i % 36;
        int gy = y0 - 2 + r, gx = x0 - 2 + c;
        float v = 0.f;
        if (gy >= 0 && gy < H && gx >= 0 && gx < W)
            v = u[((b * H) + gy) * W + gx];
        s_u[i] = v;
    }
    __syncthreads();

    const int tx = tid & 31, ty = tid >> 5;
#pragma unroll
    for (int k = 0; k < 4; ++k) {
        const int py = ty + 8 * k;
        float acc[8];
#pragma unroll
        for (int c = 0; c < 8; ++c) acc[c] = 0.f;
#pragma unroll
        for (int t = 0; t < 25; ++t) {
            int dy = t / 5, dx = t % 5;
            float v = s_u[(py + dy) * 36 + tx + dx];
#pragma unroll
            for (int c = 0; c < 8; ++c) acc[c] = fmaf(v, s_w[t * 8 + c], acc[c]);
        }
        float* dst = g_c0 + (((b * H) + (y0 + py)) * W + (x0 + tx)) * 8;
        ((float4*)dst)[0] = make_float4(acc[0], acc[1], acc[2], acc[3]);
        ((float4*)dst)[1] = make_float4(acc[4], acc[5], acc[6], acc[7]);
    }
}

// ---------------- ring kernel: c1 = conv5x5 8->8 of c0, planar smem (conflict-free) ----------------
__global__ void k_c1(const float* __restrict__ k1) {
    __shared__ __align__(16) float s_t[8 * 1296]; // planar [ci][36*36] = 41472 B
    __shared__ __align__(16) float s_w[1600];

    const int b = blockIdx.y;
    int bx, by; ring_tile(blockIdx.x, bx, by);
    const int x0 = bx * TS, y0 = by * TS;
    const int tid = threadIdx.x;

    for (int i = tid; i < 1600; i += NTHREADS) s_w[i] = k1[i];
    for (int i = tid; i < 1296; i += NTHREADS) {
        int r = i / 36, c = i % 36;
        int gy = y0 - 2 + r, gx = x0 - 2 + c;
        float4 a = make_float4(0.f, 0.f, 0.f, 0.f);
        float4 bb = make_float4(0.f, 0.f, 0.f, 0.f);
        if (gy >= 0 && gy < H && gx >= 0 && gx < W) {
            const float4* p = (const float4*)(g_c0 + (((b * H) + gy) * W + gx) * 8);
            a = p[0];
            bb = p[1];
        }
        s_t[0 * 1296 + i] = a.x;  s_t[1 * 1296 + i] = a.y;
        s_t[2 * 1296 + i] = a.z;  s_t[3 * 1296 + i] = a.w;
        s_t[4 * 1296 + i] = bb.x; s_t[5 * 1296 + i] = bb.y;
        s_t[6 * 1296 + i] = bb.z; s_t[7 * 1296 + i] = bb.w;
    }
    __syncthreads();

    const int tx = tid & 31, ty = tid >> 5;
    ull acc[4][4];
#pragma unroll
    for (int p = 0; p < 4; ++p)
#pragma unroll
        for (int j = 0; j < 4; ++j) acc[p][j] = 0ull;

#pragma unroll 1
    for (int ky = 0; ky < 5; ++ky) {
#pragma unroll
        for (int kx = 0; kx < 5; ++kx) {
            const float* wp = s_w + (ky * 5 + kx) * 64;
            const int tbase = (ty + ky) * 36 + tx + kx;
#pragma unroll
            for (int ci = 0; ci < 8; ++ci) {
                ulonglong2 wA = *(const ulonglong2*)(wp + ci * 8);
                ulonglong2 wB = *(const ulonglong2*)(wp + ci * 8 + 4);
                const float* pl = s_t + ci * 1296 + tbase;
                float v0 = pl[0];
                float v1 = pl[8 * 36];
                float v2 = pl[16 * 36];
                float v3 = pl[24 * 36];
                ull p;
                p = pack2(v0, v0);
                fma2(acc[0][0], p, wA.x); fma2(acc[0][1], p, wA.y);
                fma2(acc[0][2], p, wB.x); fma2(acc[0][3], p, wB.y);
                p = pack2(v1, v1);
                fma2(acc[1][0], p, wA.x); fma2(acc[1][1], p, wA.y);
                fma2(acc[1][2], p, wB.x); fma2(acc[1][3], p, wB.y);
                p = pack2(v2, v2);
                fma2(acc[2][0], p, wA.x); fma2(acc[2][1], p, wA.y);
                fma2(acc[2][2], p, wB.x); fma2(acc[2][3], p, wB.y);
                p = pack2(v3, v3);
                fma2(acc[3][0], p, wA.x); fma2(acc[3][1], p, wA.y);
                fma2(acc[3][2], p, wB.x); fma2(acc[3][3], p, wB.y);
            }
        }
    }

#pragma unroll
    for (int k = 0; k < 4; ++k) {
        int y = y0 + ty + 8 * k;
        float2 a0 = unpack2(acc[k][0]);
        float2 a1 = unpack2(acc[k][1]);
        float2 a2 = unpack2(acc[k][2]);
        float2 a3 = unpack2(acc[k][3]);
        float* dst = g_c1 + (((b * H) + y) * W + (x0 + tx)) * 8;
        ((float4*)dst)[0] = make_float4(a0.x, a0.y, a1.x, a1.y);
        ((float4*)dst)[1] = make_float4(a2.x, a2.y, a3.x, a3.y);
    }
}

// ---------------- ring kernel: kpre(ring px) = conv3x3(c1, k2s) * kap, planar smem ----------------
__global__ void k_c2k(const float* __restrict__ kap) {
    __shared__ __align__(16) float s_t[8 * 1156]; // planar [ci][34*34] = 36992 B
    __shared__ float s_k[72];

    const int b = blockIdx.y;
    int bx, by; ring_tile(blockIdx.x, bx, by);
    const int x0 = bx * TS, y0 = by * TS;
    const int tid = threadIdx.x;

    for (int i = tid; i < 72; i += NTHREADS) s_k[i] = g_k2s[i];
    for (int i = tid; i < 1156; i += NTHREADS) {
        int r = i / 34, c = i % 34;
        int gy = y0 - 1 + r, gx = x0 - 1 + c;
        float4 a = make_float4(0.f, 0.f, 0.f, 0.f);
        float4 bb = make_float4(0.f, 0.f, 0.f, 0.f);
        if (gy >= 0 && gy < H && gx >= 0 && gx < W) {
            const float4* p = (const float4*)(g_c1 + (((b * H) + gy) * W + gx) * 8);
            a = p[0];
            bb = p[1];
        }
        s_t[0 * 1156 + i] = a.x;  s_t[1 * 1156 + i] = a.y;
        s_t[2 * 1156 + i] = a.z;  s_t[3 * 1156 + i] = a.w;
        s_t[4 * 1156 + i] = bb.x; s_t[5 * 1156 + i] = bb.y;
        s_t[6 * 1156 + i] = bb.z; s_t[7 * 1156 + i] = bb.w;
    }
    __syncthreads();

    const int tx = tid & 31, ty = tid >> 5;
#pragma unroll
    for (int k = 0; k < 4; ++k) {
        const int py = ty + 8 * k;
        float acc = 0.f;
#pragma unroll
        for (int t = 0; t < 9; ++t) {
            int dy = t / 3, dx = t % 3;
            const int idx = (py + dy) * 34 + tx + dx;
#pragma unroll
            for (int ci = 0; ci < 8; ++ci)
                acc = fmaf(s_t[ci * 1156 + idx], s_k[t * 8 + ci], acc);
        }
        int y = y0 + py, x = x0 + tx;
        // only border band (dist < 5) differs from the composed conv
        if (y < 5 || y >= H - 5 || x < 5 || x >= W - 5)
            g_kpre[((b * H) + y) * W + x] = acc * kap[y * W + x];
    }
}

// ---------------- final fused kernel: edges in-tile (OOB-masked), grads (f32x2 px-pairs), diffs, smoother, sum ----------------
__global__ void k_final(const float* __restrict__ u,
                        const float* __restrict__ image,
                        const float* __restrict__ wx,  // (3,3,1,32) -> [t*32+co]
                        const float* __restrict__ wy,
                        const float* __restrict__ dw,  // (3,3,1,8)
                        const float* __restrict__ pw,  // (1,1,8,8)
                        const float* __restrict__ ws,  // (5,5,1,1)
                        float* __restrict__ out) {
    __shared__ __align__(16) float s_img[36 * 36];
    __shared__ __align__(16) float s_e[34 * 34];
    __shared__ __align__(16) ull   s_e2[26 * 34];
    __shared__ __align__(16) float s_u[34 * 34];
    __shared__ __align__(16) float s_kp[36 * 36];
    __shared__ __align__(16) ull   s_wx2[288];
    __shared__ __align__(16) ull   s_wy2[288];
    __shared__ float s_ws[25];
    __shared__ float s_dw[72];
    __shared__ float s_pw[64];

    const int b = blockIdx.z;
    const int x0 = blockIdx.x * TS, y0 = blockIdx.y * TS;
    const int tid = threadIdx.x;

    for (int i = tid; i < 288; i += NTHREADS) {
        float a = wx[i], c = wy[i];
        s_wx2[i] = pack2(a, a);
        s_wy2[i] = pack2(c, c);
    }
    for (int i = tid; i < 72; i += NTHREADS) s_dw[i] = dw[i];
    for (int i = tid; i < 64; i += NTHREADS) s_pw[i] = pw[i];
    for (int i = tid; i < 25; i += NTHREADS) s_ws[i] = ws[i];
    for (int i = tid; i < 36 * 36; i += NTHREADS) {
        int r = i / 36, c = i % 36;
        int gy = y0 - 2 + r, gx = x0 - 2 + c;
        float vi = 0.f, vk = 0.f;
        if (gy >= 0 && gy < H && gx >= 0 && gx < W) {
            int idx = ((b * H) + gy) * W + gx;
            vi = image[idx];
            vk = g_kpre[idx];
        }
        s_img[i] = vi;
        s_kp[i] = vk;
    }
    for (int i = tid; i < 34 * 34; i += NTHREADS) {
        int r = i / 34, c = i % 34;
        int gy = y0 - 1 + r, gx = x0 - 1 + c;
        float v = 0.f;
        if (gy >= 0 && gy < H && gx >= 0 && gx < W)
            v = u[((b * H) + gy) * W + gx];
        s_u[i] = v;
    }
    __syncthreads();

    // edges = softsign(sum_co relu(pw(dw(image))))
    // CRITICAL: edges is only defined on the image grid; the gradient convs see
    // zero-padded edges. Halo positions outside the image MUST be 0, even though
    // their dw window overlaps the image.
    for (int i = tid; i < 34 * 34; i += NTHREADS) {
        int r = i / 34, c = i % 34;
        int gy = y0 - 1 + r, gx = x0 - 1 + c;
        float ed = 0.f;
        if (gy >= 0 && gy < H && gx >= 0 && gx < W) {
            float e1[8];
#pragma unroll
            for (int ch = 0; ch < 8; ++ch) e1[ch] = 0.f;
#pragma unroll
            for (int t = 0; t < 9; ++t) {
                float v = s_img[(r + t / 3) * 36 + c + t % 3];
#pragma unroll
                for (int ch = 0; ch < 8; ++ch) e1[ch] = fmaf(v, s_dw[t * 8 + ch], e1[ch]);
            }
            float s = 0.f;
#pragma unroll
            for (int co = 0; co < 8; ++co) {
                float e2 = 0.f;
#pragma unroll
                for (int ci = 0; ci < 8; ++ci) e2 = fmaf(e1[ci], s_pw[ci * 8 + co], e2);
                s += fmaxf(e2, 0.f);
            }
            ed = s / (1.f + fabsf(s));
        }
        s_e[i] = ed;
    }
    __syncthreads();
    for (int i = tid; i < 26 * 34; i += NTHREADS)
        s_e2[i] = pack2(s_e[i], s_e[i + 8 * 34]);
    __syncthreads();

    const int tx = tid & 31, ty = tid >> 5;

    // gradient convs: 32 out channels, f32x2 lanes = pixel pairs (py, py+8)
    ull tap2[2][9];
#pragma unroll
    for (int pair = 0; pair < 2; ++pair)
#pragma unroll
        for (int t = 0; t < 9; ++t)
            tap2[pair][t] = s_e2[(ty + 16 * pair + t / 3) * 34 + tx + t % 3];

    float gxa[4] = {0.f, 0.f, 0.f, 0.f};
    float gya[4] = {0.f, 0.f, 0.f, 0.f};
#pragma unroll 1
    for (int co = 0; co < 32; ++co) {
        ull wx9[9], wy9[9];
#pragma unroll
        for (int t = 0; t < 9; ++t) {
            wx9[t] = s_wx2[t * 32 + co];
            wy9[t] = s_wy2[t * 32 + co];
        }
#pragma unroll
        for (int pair = 0; pair < 2; ++pair) {
            ull ax = 0ull, ay = 0ull;
#pragma unroll
            for (int t = 0; t < 9; ++t) {
                fma2(ax, tap2[pair][t], wx9[t]);
                fma2(ay, tap2[pair][t], wy9[t]);
            }
            float2 rx = unpack2(ax);
            float2 ry = unpack2(ay);
            gxa[2 * pair]     += fmaxf(rx.x, 0.f);
            gxa[2 * pair + 1] += fmaxf(rx.y, 0.f);
            gya[2 * pair]     += fmaxf(ry.x, 0.f);
            gya[2 * pair + 1] += fmaxf(ry.y, 0.f);
        }
    }

#pragma unroll
    for (int k = 0; k < 4; ++k) {
        const int py = ty + 8 * ((k & 1) ? 1 : 0) + 16 * (k >> 1);
        // k=0 -> ty, k=1 -> ty+8, k=2 -> ty+16, k=3 -> ty+24
        const int ec = (py + 1) * 34 + tx + 1;
        float uc = s_u[ec];
        float xp = uc - s_u[ec - 1];
        float xn = s_u[ec + 1] - uc;
        float yn = s_u[ec - 34] - uc;
        float yp = uc - s_u[ec + 34];

        float kp = 0.f;
#pragma unroll
        for (int t = 0; t < 25; ++t)
            kp = fmaf(s_kp[(py + t / 5) * 36 + tx + t % 5], s_ws[t], kp);

        float gx = gxa[k], gy = gya[k];
        float fxp = fmaxf(gx, 0.f), fxn = fminf(gx, 0.f);
        float fyp = fmaxf(gy, 0.f), fyn = fminf(gy, 0.f);

        float r = uc + fxp * xp + fxn * xn + fyp * yp + fyn * yn + s_e[ec] + kp;
        out[((b * H) + (y0 + py)) * W + (x0 + tx)] = r;
    }
}

// ---------------- launch ----------------
extern "C" void kernel_launch(void* const* d_in, const int* in_sizes, int n_in,
                              void* d_out, int out_size) {
    (void)in_sizes; (void)n_in; (void)out_size;
    const float* u     = (const float*)d_in[0];
    const float* image = (const float*)d_in[1];
    const float* wx    = (const float*)d_in[2];
    const float* wy    = (const float*)d_in[3];
    const float* dw    = (const float*)d_in[4];
    const float* pw    = (const float*)d_in[5];
    const float* k0    = (const float*)d_in[6];
    const float* k1    = (const float*)d_in[7];
    const float* k2    = (const float*)d_in[8];
    const float* ws    = (const float*)d_in[9];
    const float* kap   = (const float*)d_in[10];
    float* out = (float*)d_out;

    dim3 gridF(W / TS, H / TS, B);
    dim3 gridR(60, B);
    dim3 blk(NTHREADS);

    k_compose<<<1, 648>>>(k0, k1, k2);
    k_kpre<<<gridF, blk>>>(u, kap);      // composed 11x11 conv everywhere
    k_c0<<<gridR, blk>>>(u, k0);         // exact staged pipeline on border tiles only
    k_c1<<<gridR, blk>>>(k1);
    k_c2k<<<gridR, blk>>>(kap);          // overwrites border band (dist<5) of g_kpre
    k_final<<<gridF, blk>>>(u, image, wx, wy, dw, pw, ws, out);
}

// round 4
// speedup vs baseline: 3.4074x; 1.2963x over previous
#include <cuda_runtime.h>
#include <cstdint>

typedef unsigned long long ull;

#define B 8
#define H 512
#define W 512
#define TS 32
#define NTHREADS 256

// ---------------- device scratch (allocation-free) ----------------
__device__ float g_c0[B * H * W * 8];
__device__ float g_c1[B * H * W * 8];
__device__ float g_kpre[B * H * W];
__device__ float g_k2s[72];
__device__ float g_kc[121];

// ---------------- f32x2 packed helpers (sm_100+) ----------------
__device__ __forceinline__ ull pack2(float lo, float hi) {
    ull r;
    asm("mov.b64 %0, {%1, %2};" : "=l"(r) : "f"(lo), "f"(hi));
    return r;
}
__device__ __forceinline__ float2 unpack2(ull v) {
    float2 r;
    asm("mov.b64 {%0, %1}, %2;" : "=f"(r.x), "=f"(r.y) : "l"(v));
    return r;
}
__device__ __forceinline__ void fma2(ull& acc, ull a, ull b) {
    asm("fma.rn.f32x2 %0, %1, %2, %0;" : "+l"(acc) : "l"(a), "l"(b));
}

// ---------------- border strip decode: 64 blocks cover a band of width bw ----------------
__device__ __forceinline__ void strip_region(int id, int bw,
                                             int& y0, int& x0, int& rh, int& rw) {
    int seg = id >> 4, s = id & 15;
    if (seg == 0)      { y0 = 0;      x0 = 32 * s; rh = bw; rw = 32; }
    else if (seg == 1) { y0 = H - bw; x0 = 32 * s; rh = bw; rw = 32; }
    else if (seg == 2) { y0 = 32 * s; x0 = 0;      rh = 32; rw = bw; }
    else               { y0 = 32 * s; x0 = W - bw; rh = 32; rw = bw; }
}

// ---------------- kernel: compose k0(5x5,1->8) o k1(5x5,8->8) o sum16(k2)(3x3,8->1) -> 11x11 ----------------
__global__ void k_compose(const float* __restrict__ k0,
                          const float* __restrict__ k1,
                          const float* __restrict__ k2) {
    __shared__ float s_k2s[72];
    __shared__ float s_K01[648]; // [ry(9)][rx(9)][c2(8)]
    const int tid = threadIdx.x;

    if (tid < 72) {
        float s = 0.f;
#pragma unroll
        for (int o = 0; o < 16; ++o) s += k2[tid * 16 + o];
        s_k2s[tid] = s;
        g_k2s[tid] = s;
    }
    __syncthreads();

    if (tid < 648) {
        int c2 = tid & 7;
        int rx = (tid >> 3) % 9;
        int ry = tid / 72;
        float v = 0.f;
        int sy0 = ry - 4 > 0 ? ry - 4 : 0, sy1 = ry < 4 ? ry : 4;
        int sx0 = rx - 4 > 0 ? rx - 4 : 0, sx1 = rx < 4 ? rx : 4;
        for (int sy = sy0; sy <= sy1; ++sy)
            for (int sx = sx0; sx <= sx1; ++sx) {
                int ty = ry - sy, txx = rx - sx;
                for (int c1 = 0; c1 < 8; ++c1)
                    v += k0[(sy * 5 + sx) * 8 + c1] *
                         k1[((ty * 5 + txx) * 8 + c1) * 8 + c2];
            }
        s_K01[(ry * 9 + rx) * 8 + c2] = v;
    }
    __syncthreads();

    if (tid < 121) {
        int fx = tid % 11, fy = tid / 11;
        float v = 0.f;
        int ry0 = fy - 2 > 0 ? fy - 2 : 0, ry1 = fy < 8 ? fy : 8;
        int rx0 = fx - 2 > 0 ? fx - 2 : 0, rx1 = fx < 8 ? fx : 8;
        for (int ry = ry0; ry <= ry1; ++ry)
            for (int rx = rx0; rx <= rx1; ++rx) {
                int vy = fy - ry, vx = fx - rx;
                for (int c2 = 0; c2 < 8; ++c2)
                    v += s_K01[(ry * 9 + rx) * 8 + c2] *
                         s_k2s[(vy * 3 + vx) * 8 + c2];
            }
        g_kc[tid] = v;
    }
}

// ---------------- kernel: kpre = conv11x11(u, g_kc) * kappa_kernel (register-sliding f32x2) ----------------
// 128 threads = 32(x) x 4(ty); each thread computes 8 consecutive-y outputs as 4 pairs.
__global__ void k_kpre(const float* __restrict__ u, const float* __restrict__ kap) {
    __shared__ __align__(16) float s_t[42 * 42];
    __shared__ __align__(16) ull   s_K2[121];

    const int b = blockIdx.z;
    const int x0 = blockIdx.x * TS, y0 = blockIdx.y * TS;
    const int tid = threadIdx.x;

    for (int i = tid; i < 121; i += 128) {
        float w = g_kc[i];
        s_K2[i] = pack2(w, w);
    }
    for (int i = tid; i < 42 * 42; i += 128) {
        int r = i / 42, c = i % 42;
        int gy = y0 - 5 + r, gx = x0 - 5 + c;
        float v = 0.f;
        if (gy >= 0 && gy < H && gx >= 0 && gx < W)
            v = u[((b * H) + gy) * W + gx];
        s_t[i] = v;
    }
    __syncthreads();

    const int tx = tid & 31, ty = tid >> 5;
    const int r0 = ty * 8;

    ull acc[4] = {0ull, 0ull, 0ull, 0ull};

#pragma unroll 1
    for (int dx = 0; dx < 11; ++dx) {
        float t[18];
        const float* col = s_t + r0 * 42 + tx + dx;
#pragma unroll
        for (int i = 0; i < 18; ++i) t[i] = col[i * 42];
        ull pk[17];
#pragma unroll
        for (int i = 0; i < 17; ++i) pk[i] = pack2(t[i], t[i + 1]);
#pragma unroll
        for (int dy = 0; dy < 11; ++dy) {
            ull w = s_K2[dy * 11 + dx];
            fma2(acc[0], pk[dy],     w);
            fma2(acc[1], pk[dy + 2], w);
            fma2(acc[2], pk[dy + 4], w);
            fma2(acc[3], pk[dy + 6], w);
        }
    }

    const int x = x0 + tx;
#pragma unroll
    for (int p = 0; p < 4; ++p) {
        float2 r = unpack2(acc[p]);
        int y = y0 + r0 + 2 * p;
        g_kpre[((b * H) + y) * W + x]     = r.x * kap[y * W + x];
        g_kpre[((b * H) + y + 1) * W + x] = r.y * kap[(y + 1) * W + x];
    }
}

// ---------------- strip kernel: c0 = conv5x5 1->8 of u on border band (bw=10) ----------------
__global__ void k_c0s(const float* __restrict__ u, const float* __restrict__ k0) {
    __shared__ __align__(16) float s_u[36 * 14 > 14 * 36 ? 36 * 14 : 14 * 36]; // 504
    __shared__ float s_w[200];

    const int b = blockIdx.y;
    int y0, x0, rh, rw;
    strip_region(blockIdx.x, 10, y0, x0, rh, rw);
    const int th = rh + 4, tw = rw + 4;
    const int tid = threadIdx.x;

    for (int i = tid; i < 200; i += NTHREADS) s_w[i] = k0[i];
    for (int i = tid; i < th * tw; i += NTHREADS) {
        int r = i / tw, c = i % tw;
        int gy = y0 - 2 + r, gx = x0 - 2 + c;
        float v = 0.f;
        if (gy >= 0 && gy < H && gx >= 0 && gx < W)
            v = u[((b * H) + gy) * W + gx];
        s_u[i] = v;
    }
    __syncthreads();

    for (int i = tid; i < rh * rw; i += NTHREADS) {
        int py = i / rw, px = i % rw;
        float acc[8];
#pragma unroll
        for (int c = 0; c < 8; ++c) acc[c] = 0.f;
#pragma unroll
        for (int t = 0; t < 25; ++t) {
            int dy = t / 5, dx = t % 5;
            float v = s_u[(py + dy) * tw + px + dx];
#pragma unroll
            for (int c = 0; c < 8; ++c) acc[c] = fmaf(v, s_w[t * 8 + c], acc[c]);
        }
        float* dst = g_c0 + (((b * H) + (y0 + py)) * W + (x0 + px)) * 8;
        ((float4*)dst)[0] = make_float4(acc[0], acc[1], acc[2], acc[3]);
        ((float4*)dst)[1] = make_float4(acc[4], acc[5], acc[6], acc[7]);
    }
}

// ---------------- strip kernel: c1 = conv5x5 8->8 of c0 on border band (bw=6) ----------------
__global__ void k_c1s(const float* __restrict__ k1) {
    __shared__ __align__(16) float s_t[8 * 360]; // planar [ci][(rh+4)*(rw+4)] max 360
    __shared__ __align__(16) float s_w[1600];

    const int b = blockIdx.y;
    int y0, x0, rh, rw;
    strip_region(blockIdx.x, 6, y0, x0, rh, rw);
    const int th = rh + 4, tw = rw + 4;
    const int npx = th * tw;
    const int tid = threadIdx.x;

    for (int i = tid; i < 1600; i += NTHREADS) s_w[i] = k1[i];
    for (int i = tid; i < npx; i += NTHREADS) {
        int r = i / tw, c = i % tw;
        int gy = y0 - 2 + r, gx = x0 - 2 + c;
        float4 a = make_float4(0.f, 0.f, 0.f, 0.f);
        float4 bb = make_float4(0.f, 0.f, 0.f, 0.f);
        if (gy >= 0 && gy < H && gx >= 0 && gx < W) {
            const float4* p = (const float4*)(g_c0 + (((b * H) + gy) * W + gx) * 8);
            a = p[0];
            bb = p[1];
        }
        s_t[0 * npx + i] = a.x;  s_t[1 * npx + i] = a.y;
        s_t[2 * npx + i] = a.z;  s_t[3 * npx + i] = a.w;
        s_t[4 * npx + i] = bb.x; s_t[5 * npx + i] = bb.y;
        s_t[6 * npx + i] = bb.z; s_t[7 * npx + i] = bb.w;
    }
    __syncthreads();

    for (int i = tid; i < rh * rw; i += NTHREADS) {
        int py = i / rw, px = i % rw;
        ull acc[4] = {0ull, 0ull, 0ull, 0ull};
#pragma unroll 1
        for (int t = 0; t < 25; ++t) {
            int dy = t / 5, dx = t % 5;
            const int base = (py + dy) * tw + px + dx;
            const float* wp = s_w + t * 64;
#pragma unroll
            for (int ci = 0; ci < 8; ++ci) {
                ulonglong2 wA = *(const ulonglong2*)(wp + ci * 8);
                ulonglong2 wB = *(const ulonglong2*)(wp + ci * 8 + 4);
                float v = s_t[ci * npx + base];
                ull p = pack2(v, v);
                fma2(acc[0], p, wA.x); fma2(acc[1], p, wA.y);
                fma2(acc[2], p, wB.x); fma2(acc[3], p, wB.y);
            }
        }
        float2 a0 = unpack2(acc[0]);
        float2 a1 = unpack2(acc[1]);
        float2 a2 = unpack2(acc[2]);
        float2 a3 = unpack2(acc[3]);
        float* dst = g_c1 + (((b * H) + (y0 + py)) * W + (x0 + px)) * 8;
        ((float4*)dst)[0] = make_float4(a0.x, a0.y, a1.x, a1.y);
        ((float4*)dst)[1] = make_float4(a2.x, a2.y, a3.x, a3.y);
    }
}

// ---------------- strip kernel: kpre(band px) = conv3x3(c1, k2s) * kap (bw=5) ----------------
__global__ void k_c2ks(const float* __restrict__ kap) {
    __shared__ __align__(16) float s_t[8 * 238]; // planar [ci][(rh+2)*(rw+2)] max 238
    __shared__ float s_k[72];

    const int b = blockIdx.y;
    int y0, x0, rh, rw;
    strip_region(blockIdx.x, 5, y0, x0, rh, rw);
    const int th = rh + 2, tw = rw + 2;
    const int npx = th * tw;
    const int tid = threadIdx.x;

    for (int i = tid; i < 72; i += NTHREADS) s_k[i] = g_k2s[i];
    for (int i = tid; i < npx; i += NTHREADS) {
        int r = i / tw, c = i % tw;
        int gy = y0 - 1 + r, gx = x0 - 1 + c;
        float4 a = make_float4(0.f, 0.f, 0.f, 0.f);
        float4 bb = make_float4(0.f, 0.f, 0.f, 0.f);
        if (gy >= 0 && gy < H && gx >= 0 && gx < W) {
            const float4* p = (const float4*)(g_c1 + (((b * H) + gy) * W + gx) * 8);
            a = p[0];
            bb = p[1];
        }
        s_t[0 * npx + i] = a.x;  s_t[1 * npx + i] = a.y;
        s_t[2 * npx + i] = a.z;  s_t[3 * npx + i] = a.w;
        s_t[4 * npx + i] = bb.x; s_t[5 * npx + i] = bb.y;
        s_t[6 * npx + i] = bb.z; s_t[7 * npx + i] = bb.w;
    }
    __syncthreads();

    for (int i = tid; i < rh * rw; i += NTHREADS) {
        int py = i / rw, px = i % rw;
        float acc = 0.f;
#pragma unroll
        for (int t = 0; t < 9; ++t) {
            int dy = t / 3, dx = t % 3;
            const int idx = (py + dy) * tw + px + dx;
#pragma unroll
            for (int ci = 0; ci < 8; ++ci)
                acc = fmaf(s_t[ci * npx + idx], s_k[t * 8 + ci], acc);
        }
        int y = y0 + py, x = x0 + px;
        g_kpre[((b * H) + y) * W + x] = acc * kap[y * W + x];
    }
}

// ---------------- final fused kernel: edges in-tile (OOB-masked), grads (f32x2 px-pairs), diffs, smoother, sum ----------------
__global__ void k_final(const float* __restrict__ u,
                        const float* __restrict__ image,
                        const float* __restrict__ wx,  // (3,3,1,32) -> [t*32+co]
                        const float* __restrict__ wy,
                        const float* __restrict__ dw,  // (3,3,1,8)
                        const float* __restrict__ pw,  // (1,1,8,8)
                        const float* __restrict__ ws,  // (5,5,1,1)
                        float* __restrict__ out) {
    __shared__ __align__(16) float s_img[36 * 36];
    __shared__ __align__(16) float s_e[34 * 34];
    __shared__ __align__(16) ull   s_e2[26 * 34];
    __shared__ __align__(16) float s_u[34 * 34];
    __shared__ __align__(16) float s_kp[36 * 36];
    __shared__ __align__(16) ull   s_wx2[288];
    __shared__ __align__(16) ull   s_wy2[288];
    __shared__ float s_ws[25];
    __shared__ float s_dw[72];
    __shared__ float s_pw[64];

    const int b = blockIdx.z;
    const int x0 = blockIdx.x * TS, y0 = blockIdx.y * TS;
    const int tid = threadIdx.x;

    for (int i = tid; i < 288; i += NTHREADS) {
        float a = wx[i], c = wy[i];
        s_wx2[i] = pack2(a, a);
        s_wy2[i] = pack2(c, c);
    }
    for (int i = tid; i < 72; i += NTHREADS) s_dw[i] = dw[i];
    for (int i = tid; i < 64; i += NTHREADS) s_pw[i] = pw[i];
    for (int i = tid; i < 25; i += NTHREADS) s_ws[i] = ws[i];
    for (int i = tid; i < 36 * 36; i += NTHREADS) {
        int r = i / 36, c = i % 36;
        int gy = y0 - 2 + r, gx = x0 - 2 + c;
        float vi = 0.f, vk = 0.f;
        if (gy >= 0 && gy < H && gx >= 0 && gx < W) {
            int idx = ((b * H) + gy) * W + gx;
            vi = image[idx];
            vk = g_kpre[idx];
        }
        s_img[i] = vi;
        s_kp[i] = vk;
    }
    for (int i = tid; i < 34 * 34; i += NTHREADS) {
        int r = i / 34, c = i % 34;
        int gy = y0 - 1 + r, gx = x0 - 1 + c;
        float v = 0.f;
        if (gy >= 0 && gy < H && gx >= 0 && gx < W)
            v = u[((b * H) + gy) * W + gx];
        s_u[i] = v;
    }
    __syncthreads();

    // edges = softsign(sum_co relu(pw(dw(image)))) — OOB halo positions MUST stay 0
    for (int i = tid; i < 34 * 34; i += NTHREADS) {
        int r = i / 34, c = i % 34;
        int gy = y0 - 1 + r, gx = x0 - 1 + c;
        float ed = 0.f;
        if (gy >= 0 && gy < H && gx >= 0 && gx < W) {
            float e1[8];
#pragma unroll
            for (int ch = 0; ch < 8; ++ch) e1[ch] = 0.f;
#pragma unroll
            for (int t = 0; t < 9; ++t) {
                float v = s_img[(r + t / 3) * 36 + c + t % 3];
#pragma unroll
                for (int ch = 0; ch < 8; ++ch) e1[ch] = fmaf(v, s_dw[t * 8 + ch], e1[ch]);
            }
            float s = 0.f;
#pragma unroll
            for (int co = 0; co < 8; ++co) {
                float e2 = 0.f;
#pragma unroll
                for (int ci = 0; ci < 8; ++ci) e2 = fmaf(e1[ci], s_pw[ci * 8 + co], e2);
                s += fmaxf(e2, 0.f);
            }
            ed = s / (1.f + fabsf(s));
        }
        s_e[i] = ed;
    }
    __syncthreads();
    for (int i = tid; i < 26 * 34; i += NTHREADS)
        s_e2[i] = pack2(s_e[i], s_e[i + 8 * 34]);
    __syncthreads();

    const int tx = tid & 31, ty = tid >> 5;

    // gradient convs: 32 out channels, f32x2 lanes = pixel pairs (py, py+8)
    ull tap2[2][9];
#pragma unroll
    for (int pair = 0; pair < 2; ++pair)
#pragma unroll
        for (int t = 0; t < 9; ++t)
            tap2[pair][t] = s_e2[(ty + 16 * pair + t / 3) * 34 + tx + t % 3];

    float gxa[4] = {0.f, 0.f, 0.f, 0.f};
    float gya[4] = {0.f, 0.f, 0.f, 0.f};
#pragma unroll 1
    for (int co = 0; co < 32; ++co) {
        ull wx9[9], wy9[9];
#pragma unroll
        for (int t = 0; t < 9; ++t) {
            wx9[t] = s_wx2[t * 32 + co];
            wy9[t] = s_wy2[t * 32 + co];
        }
#pragma unroll
        for (int pair = 0; pair < 2; ++pair) {
            ull ax = 0ull, ay = 0ull;
#pragma unroll
            for (int t = 0; t < 9; ++t) {
                fma2(ax, tap2[pair][t], wx9[t]);
                fma2(ay, tap2[pair][t], wy9[t]);
            }
            float2 rx = unpack2(ax);
            float2 ry = unpack2(ay);
            gxa[2 * pair]     += fmaxf(rx.x, 0.f);
            gxa[2 * pair + 1] += fmaxf(rx.y, 0.f);
            gya[2 * pair]     += fmaxf(ry.x, 0.f);
            gya[2 * pair + 1] += fmaxf(ry.y, 0.f);
        }
    }

#pragma unroll
    for (int k = 0; k < 4; ++k) {
        // k=0 -> ty, k=1 -> ty+8, k=2 -> ty+16, k=3 -> ty+24
        const int py = ty + 8 * (k & 1) + 16 * (k >> 1);
        const int ec = (py + 1) * 34 + tx + 1;
        float uc = s_u[ec];
        float xp = uc - s_u[ec - 1];
        float xn = s_u[ec + 1] - uc;
        float yn = s_u[ec - 34] - uc;
        float yp = uc - s_u[ec + 34];

        float kp = 0.f;
#pragma unroll
        for (int t = 0; t < 25; ++t)
            kp = fmaf(s_kp[(py + t / 5) * 36 + tx + t % 5], s_ws[t], kp);

        float gx = gxa[k], gy = gya[k];
        float fxp = fmaxf(gx, 0.f), fxn = fminf(gx, 0.f);
        float fyp = fmaxf(gy, 0.f), fyn = fminf(gy, 0.f);

        float r = uc + fxp * xp + fxn * xn + fyp * yp + fyn * yn + s_e[ec] + kp;
        out[((b * H) + (y0 + py)) * W + (x0 + tx)] = r;
    }
}

// ---------------- launch ----------------
extern "C" void kernel_launch(void* const* d_in, const int* in_sizes, int n_in,
                              void* d_out, int out_size) {
    (void)in_sizes; (void)n_in; (void)out_size;
    const float* u     = (const float*)d_in[0];
    const float* image = (const float*)d_in[1];
    const float* wx    = (const float*)d_in[2];
    const float* wy    = (const float*)d_in[3];
    const float* dw    = (const float*)d_in[4];
    const float* pw    = (const float*)d_in[5];
    const float* k0    = (const float*)d_in[6];
    const float* k1    = (const float*)d_in[7];
    const float* k2    = (const float*)d_in[8];
    const float* ws    = (const float*)d_in[9];
    const float* kap   = (const float*)d_in[10];
    float* out = (float*)d_out;

    dim3 gridF(W / TS, H / TS, B);
    dim3 gridS(64, B);
    dim3 blk(NTHREADS);

    k_compose<<<1, 648>>>(k0, k1, k2);
    k_kpre<<<gridF, dim3(128)>>>(u, kap);   // composed 11x11 conv everywhere (128-thr, 8px/thread)
    k_c0s<<<gridS, blk>>>(u, k0);           // staged pipeline: width-10 border band
    k_c1s<<<gridS, blk>>>(k1);              // width-6 band
    k_c2ks<<<gridS, blk>>>(kap);            // width-5 band overwrite of g_kpre
    k_final<<<gridF, blk>>>(u, image, wx, wy, dw, pw, ws, out);
}

// round 5
// speedup vs baseline: 3.5076x; 1.0294x over previous
#include <cuda_runtime.h>
#include <cstdint>

typedef unsigned long long ull;

#define B 8
#define H 512
#define W 512
#define TS 32
#define NTHREADS 256

// ---------------- device scratch (allocation-free) ----------------
__device__ float g_c0[B * H * W * 8];
__device__ float g_c1[B * H * W * 8];
__device__ float g_kpre[B * H * W];
__device__ float g_k2s[72];
__device__ float g_kc[121];

// ---------------- f32x2 packed helpers (sm_100+) ----------------
__device__ __forceinline__ ull pack2(float lo, float hi) {
    ull r;
    asm("mov.b64 %0, {%1, %2};" : "=l"(r) : "f"(lo), "f"(hi));
    return r;
}
__device__ __forceinline__ float2 unpack2(ull v) {
    float2 r;
    asm("mov.b64 {%0, %1}, %2;" : "=f"(r.x), "=f"(r.y) : "l"(v));
    return r;
}
__device__ __forceinline__ void fma2(ull& acc, ull a, ull b) {
    asm("fma.rn.f32x2 %0, %1, %2, %0;" : "+l"(acc) : "l"(a), "l"(b));
}

// ---------------- border band decode: 32 blocks/batch, 64-px segments ----------------
// seg 0: top rows [0,bw), seg 1: bottom rows [H-bw,H), seg 2: left cols [0,bw), seg 3: right.
__device__ __forceinline__ void band_region(int id, int bw,
                                            int& oy0, int& ox0, int& oR, int& oC) {
    int seg = id >> 3, s = id & 7;
    if (seg == 0)      { oy0 = 0;      ox0 = 64 * s; oR = bw; oC = 64; }
    else if (seg == 1) { oy0 = H - bw; ox0 = 64 * s; oR = bw; oC = 64; }
    else if (seg == 2) { oy0 = 64 * s; ox0 = 0;      oR = 64; oC = bw; }
    else               { oy0 = 64 * s; ox0 = W - bw; oR = 64; oC = bw; }
}

// ---------------- kernel: compose k0(5x5,1->8) o k1(5x5,8->8) o sum16(k2)(3x3,8->1) -> 11x11 ----------------
__global__ void k_compose(const float* __restrict__ k0,
                          const float* __restrict__ k1,
                          const float* __restrict__ k2) {
    __shared__ float s_k2s[72];
    __shared__ float s_K01[648]; // [ry(9)][rx(9)][c2(8)]
    const int tid = threadIdx.x;

    if (tid < 72) {
        float s = 0.f;
#pragma unroll
        for (int o = 0; o < 16; ++o) s += k2[tid * 16 + o];
        s_k2s[tid] = s;
        g_k2s[tid] = s;
    }
    __syncthreads();

    if (tid < 648) {
        int c2 = tid & 7;
        int rx = (tid >> 3) % 9;
        int ry = tid / 72;
        float v = 0.f;
        int sy0 = ry - 4 > 0 ? ry - 4 : 0, sy1 = ry < 4 ? ry : 4;
        int sx0 = rx - 4 > 0 ? rx - 4 : 0, sx1 = rx < 4 ? rx : 4;
        for (int sy = sy0; sy <= sy1; ++sy)
            for (int sx = sx0; sx <= sx1; ++sx) {
                int ty = ry - sy, txx = rx - sx;
                for (int c1 = 0; c1 < 8; ++c1)
                    v += k0[(sy * 5 + sx) * 8 + c1] *
                         k1[((ty * 5 + txx) * 8 + c1) * 8 + c2];
            }
        s_K01[(ry * 9 + rx) * 8 + c2] = v;
    }
    __syncthreads();

    if (tid < 121) {
        int fx = tid % 11, fy = tid / 11;
        float v = 0.f;
        int ry0 = fy - 2 > 0 ? fy - 2 : 0, ry1 = fy < 8 ? fy : 8;
        int rx0 = fx - 2 > 0 ? fx - 2 : 0, rx1 = fx < 8 ? fx : 8;
        for (int ry = ry0; ry <= ry1; ++ry)
            for (int rx = rx0; rx <= rx1; ++rx) {
                int vy = fy - ry, vx = fx - rx;
                for (int c2 = 0; c2 < 8; ++c2)
                    v += s_K01[(ry * 9 + rx) * 8 + c2] *
                         s_k2s[(vy * 3 + vx) * 8 + c2];
            }
        g_kc[tid] = v;
    }
}

// ---------------- kernel: kpre = conv11x11(u, g_kc) * kappa_kernel (register-sliding f32x2) ----------------
__global__ void k_kpre(const float* __restrict__ u, const float* __restrict__ kap) {
    __shared__ __align__(16) float s_t[42 * 42];
    __shared__ __align__(16) ull   s_K2[121];

    const int b = blockIdx.z;
    const int x0 = blockIdx.x * TS, y0 = blockIdx.y * TS;
    const int tid = threadIdx.x;

    for (int i = tid; i < 121; i += 128) {
        float w = g_kc[i];
        s_K2[i] = pack2(w, w);
    }
    for (int i = tid; i < 42 * 42; i += 128) {
        int r = i / 42, c = i % 42;
        int gy = y0 - 5 + r, gx = x0 - 5 + c;
        float v = 0.f;
        if (gy >= 0 && gy < H && gx >= 0 && gx < W)
            v = u[((b * H) + gy) * W + gx];
        s_t[i] = v;
    }
    __syncthreads();

    const int tx = tid & 31, ty = tid >> 5;
    const int r0 = ty * 8;

    ull acc[4] = {0ull, 0ull, 0ull, 0ull};

#pragma unroll 1
    for (int dx = 0; dx < 11; ++dx) {
        float t[18];
        const float* col = s_t + r0 * 42 + tx + dx;
#pragma unroll
        for (int i = 0; i < 18; ++i) t[i] = col[i * 42];
        ull pk[17];
#pragma unroll
        for (int i = 0; i < 17; ++i) pk[i] = pack2(t[i], t[i + 1]);
#pragma unroll
        for (int dy = 0; dy < 11; ++dy) {
            ull w = s_K2[dy * 11 + dx];
            fma2(acc[0], pk[dy],     w);
            fma2(acc[1], pk[dy + 2], w);
            fma2(acc[2], pk[dy + 4], w);
            fma2(acc[3], pk[dy + 6], w);
        }
    }

    const int x = x0 + tx;
#pragma unroll
    for (int p = 0; p < 4; ++p) {
        float2 r = unpack2(acc[p]);
        int y = y0 + r0 + 2 * p;
        g_kpre[((b * H) + y) * W + x]     = r.x * kap[y * W + x];
        g_kpre[((b * H) + y + 1) * W + x] = r.y * kap[(y + 1) * W + x];
    }
}

// ---------------- band kernel: c0 = conv5x5 1->8 of u, band 6 (dist<=5), f32x2 ----------------
__global__ void k_c0s(const float* __restrict__ u, const float* __restrict__ k0) {
    __shared__ __align__(16) float s_u[680];   // (oR+4)*(oC+4) = 10*68 or 68*10
    __shared__ __align__(16) ull   s_w2[100];  // k0 channel pairs

    const int b = blockIdx.y;
    int oy0, ox0, oR, oC;
    band_region(blockIdx.x, 6, oy0, ox0, oR, oC);
    const int TW = oC + 4;
    const int tid = threadIdx.x;

    for (int i = tid; i < 100; i += NTHREADS) {
        float2 w = ((const float2*)k0)[i];
        s_w2[i] = pack2(w.x, w.y);
    }
    for (int i = tid; i < 680; i += NTHREADS) {
        int r = i / TW, c = i % TW;
        int gy = oy0 - 2 + r, gx = ox0 - 2 + c;
        float v = 0.f;
        if (gy >= 0 && gy < H && gx >= 0 && gx < W)
            v = u[((b * H) + gy) * W + gx];
        s_u[i] = v;
    }
    __syncthreads();

    for (int i = tid; i < oR * oC; i += NTHREADS) {
        int pr = i / oC, pc = i % oC;
        ull acc[4] = {0ull, 0ull, 0ull, 0ull};
#pragma unroll
        for (int t = 0; t < 25; ++t) {
            int dy = t / 5, dx = t % 5;
            float v = s_u[(pr + dy) * TW + pc + dx];
            ull vv = pack2(v, v);
            fma2(acc[0], vv, s_w2[t * 4 + 0]);
            fma2(acc[1], vv, s_w2[t * 4 + 1]);
            fma2(acc[2], vv, s_w2[t * 4 + 2]);
            fma2(acc[3], vv, s_w2[t * 4 + 3]);
        }
        float2 a0 = unpack2(acc[0]);
        float2 a1 = unpack2(acc[1]);
        float2 a2 = unpack2(acc[2]);
        float2 a3 = unpack2(acc[3]);
        float* dst = g_c0 + (((b * H) + (oy0 + pr)) * W + (ox0 + pc)) * 8;
        ((float4*)dst)[0] = make_float4(a0.x, a0.y, a1.x, a1.y);
        ((float4*)dst)[1] = make_float4(a2.x, a2.y, a3.x, a3.y);
    }
}

// ---------------- band kernel: c1 = conv5x5 8->8 of c0, band 4 (dist<=3), pixel-pair ----------------
// 128 threads; each thread computes 2 adjacent pixels (rows for horiz strips, cols for vert),
// amortizing the broadcast weight loads 2x.
__global__ void k_c1s(const float* __restrict__ k1) {
    __shared__ __align__(16) float s_t[8 * 544]; // planar [ci][(oR+4)*(oC+4)], 8*68=68*8=544
    __shared__ __align__(16) float s_w[1600];

    const int b = blockIdx.y;
    int oy0, ox0, oR, oC;
    band_region(blockIdx.x, 4, oy0, ox0, oR, oC);
    const int TW = oC + 4;
    const int tid = threadIdx.x;

    for (int i = tid; i < 1600; i += 128) s_w[i] = k1[i];
    for (int i = tid; i < 544; i += 128) {
        int r = i / TW, c = i % TW;
        int gy = oy0 - 2 + r, gx = ox0 - 2 + c;
        float4 a = make_float4(0.f, 0.f, 0.f, 0.f);
        float4 bb = make_float4(0.f, 0.f, 0.f, 0.f);
        if (gy >= 0 && gy < H && gx >= 0 && gx < W) {
            const float4* p = (const float4*)(g_c0 + (((b * H) + gy) * W + gx) * 8);
            a = p[0];
            bb = p[1];
        }
        s_t[0 * 544 + i] = a.x;  s_t[1 * 544 + i] = a.y;
        s_t[2 * 544 + i] = a.z;  s_t[3 * 544 + i] = a.w;
        s_t[4 * 544 + i] = bb.x; s_t[5 * 544 + i] = bb.y;
        s_t[6 * 544 + i] = bb.z; s_t[7 * 544 + i] = bb.w;
    }
    __syncthreads();

    // pair decode: horiz (oC==64): 2 row-pairs x 64 cols; vert: 64 rows x 2 col-pairs
    int la, lc, step, gy0, gx0, gy1, gx1;
    if (oC == 64) {
        int pr = tid >> 6, pc = tid & 63;
        la = 2 * pr; lc = pc; step = TW;
        gy0 = oy0 + 2 * pr; gx0 = ox0 + pc;
        gy1 = gy0 + 1;      gx1 = gx0;
    } else {
        int r = tid & 63, pp = tid >> 6;
        la = r; lc = 2 * pp; step = 1;
        gy0 = oy0 + r; gx0 = ox0 + 2 * pp;
        gy1 = gy0;     gx1 = gx0 + 1;
    }

    ull acc0[4] = {0ull, 0ull, 0ull, 0ull};
    ull acc1[4] = {0ull, 0ull, 0ull, 0ull};

#pragma unroll 1
    for (int dy = 0; dy < 5; ++dy) {
#pragma unroll
        for (int dx = 0; dx < 5; ++dx) {
            const float* wp = s_w + (dy * 5 + dx) * 64;
            const int idx0 = (la + dy) * TW + lc + dx;
#pragma unroll
            for (int ci = 0; ci < 8; ++ci) {
                ulonglong2 wA = *(const ulonglong2*)(wp + ci * 8);
                ulonglong2 wB = *(const ulonglong2*)(wp + ci * 8 + 4);
                float v0 = s_t[ci * 544 + idx0];
                float v1 = s_t[ci * 544 + idx0 + step];
                ull p0 = pack2(v0, v0);
                ull p1 = pack2(v1, v1);
                fma2(acc0[0], p0, wA.x); fma2(acc0[1], p0, wA.y);
                fma2(acc0[2], p0, wB.x); fma2(acc0[3], p0, wB.y);
                fma2(acc1[0], p1, wA.x); fma2(acc1[1], p1, wA.y);
                fma2(acc1[2], p1, wB.x); fma2(acc1[3], p1, wB.y);
            }
        }
    }

    {
        float2 a0 = unpack2(acc0[0]);
        float2 a1 = unpack2(acc0[1]);
        float2 a2 = unpack2(acc0[2]);
        float2 a3 = unpack2(acc0[3]);
        float* dst = g_c1 + (((b * H) + gy0) * W + gx0) * 8;
        ((float4*)dst)[0] = make_float4(a0.x, a0.y, a1.x, a1.y);
        ((float4*)dst)[1] = make_float4(a2.x, a2.y, a3.x, a3.y);
    }
    {
        float2 a0 = unpack2(acc1[0]);
        float2 a1 = unpack2(acc1[1]);
        float2 a2 = unpack2(acc1[2]);
        float2 a3 = unpack2(acc1[3]);
        float* dst = g_c1 + (((b * H) + gy1) * W + gx1) * 8;
        ((float4*)dst)[0] = make_float4(a0.x, a0.y, a1.x, a1.y);
        ((float4*)dst)[1] = make_float4(a2.x, a2.y, a3.x, a3.y);
    }
}

// ---------------- band kernel: kpre(band px) = conv3x3(c1, k2s) * kap, band 3 (dist<=2) ----------------
__global__ void k_c2ks(const float* __restrict__ kap) {
    __shared__ __align__(16) float s_t[8 * 330]; // planar [ci][(oR+2)*(oC+2)], 5*66=330
    __shared__ float s_k[72];

    const int b = blockIdx.y;
    int oy0, ox0, oR, oC;
    band_region(blockIdx.x, 3, oy0, ox0, oR, oC);
    const int TW = oC + 2;
    const int tid = threadIdx.x;

    for (int i = tid; i < 72; i += NTHREADS) s_k[i] = g_k2s[i];
    for (int i = tid; i < 330; i += NTHREADS) {
        int r = i / TW, c = i % TW;
        int gy = oy0 - 1 + r, gx = ox0 - 1 + c;
        float4 a = make_float4(0.f, 0.f, 0.f, 0.f);
        float4 bb = make_float4(0.f, 0.f, 0.f, 0.f);
        if (gy >= 0 && gy < H && gx >= 0 && gx < W) {
            const float4* p = (const float4*)(g_c1 + (((b * H) + gy) * W + gx) * 8);
            a = p[0];
            bb = p[1];
        }
        s_t[0 * 330 + i] = a.x;  s_t[1 * 330 + i] = a.y;
        s_t[2 * 330 + i] = a.z;  s_t[3 * 330 + i] = a.w;
        s_t[4 * 330 + i] = bb.x; s_t[5 * 330 + i] = bb.y;
        s_t[6 * 330 + i] = bb.z; s_t[7 * 330 + i] = bb.w;
    }
    __syncthreads();

    for (int i = tid; i < oR * oC; i += NTHREADS) {
        int pr = i / oC, pc = i % oC;
        float acc = 0.f;
#pragma unroll
        for (int t = 0; t < 9; ++t) {
            int dy = t / 3, dx = t % 3;
            const int idx = (pr + dy) * TW + pc + dx;
#pragma unroll
            for (int ci = 0; ci < 8; ++ci)
                acc = fmaf(s_t[ci * 330 + idx], s_k[t * 8 + ci], acc);
        }
        int y = oy0 + pr, x = ox0 + pc;
        g_kpre[((b * H) + y) * W + x] = acc * kap[y * W + x];
    }
}

// ---------------- final fused kernel: edges in-tile f32x2 (OOB-masked), grads, diffs, smoother, sum ----------------
__global__ void k_final(const float* __restrict__ u,
                        const float* __restrict__ image,
                        const float* __restrict__ wx,  // (3,3,1,32) -> [t*32+co]
                        const float* __restrict__ wy,
                        const float* __restrict__ dw,  // (3,3,1,8)
                        const float* __restrict__ pw,  // (1,1,8,8)
                        const float* __restrict__ ws,  // (5,5,1,1)
                        float* __restrict__ out) {
    __shared__ __align__(16) float s_img[36 * 36];
    __shared__ __align__(16) float s_e[34 * 34];
    __shared__ __align__(16) ull   s_e2[26 * 34];
    __shared__ __align__(16) float s_u[34 * 34];
    __shared__ __align__(16) float s_kp[36 * 36];
    __shared__ __align__(16) ull   s_wx2[288];
    __shared__ __align__(16) ull   s_wy2[288];
    __shared__ __align__(16) ull   s_dw2[36];  // dw channel pairs
    __shared__ __align__(16) ull   s_pw2[32];  // pw co pairs
    __shared__ float s_ws[25];

    const int b = blockIdx.z;
    const int x0 = blockIdx.x * TS, y0 = blockIdx.y * TS;
    const int tid = threadIdx.x;

    for (int i = tid; i < 288; i += NTHREADS) {
        float a = wx[i], c = wy[i];
        s_wx2[i] = pack2(a, a);
        s_wy2[i] = pack2(c, c);
    }
    if (tid < 36) {
        float2 v = ((const float2*)dw)[tid];
        s_dw2[tid] = pack2(v.x, v.y);
    }
    if (tid >= 64 && tid < 96) {
        float2 v = ((const float2*)pw)[tid - 64];
        s_pw2[tid - 64] = pack2(v.x, v.y);
    }
    if (tid >= 128 && tid < 153) s_ws[tid - 128] = ws[tid - 128];
    for (int i = tid; i < 36 * 36; i += NTHREADS) {
        int r = i / 36, c = i % 36;
        int gy = y0 - 2 + r, gx = x0 - 2 + c;
        float vi = 0.f, vk = 0.f;
        if (gy >= 0 && gy < H && gx >= 0 && gx < W) {
            int idx = ((b * H) + gy) * W + gx;
            vi = image[idx];
            vk = g_kpre[idx];
        }
        s_img[i] = vi;
        s_kp[i] = vk;
    }
    for (int i = tid; i < 34 * 34; i += NTHREADS) {
        int r = i / 34, c = i % 34;
        int gy = y0 - 1 + r, gx = x0 - 1 + c;
        float v = 0.f;
        if (gy >= 0 && gy < H && gx >= 0 && gx < W)
            v = u[((b * H) + gy) * W + gx];
        s_u[i] = v;
    }
    __syncthreads();

    // edges = softsign(sum_co relu(pw(dw(image)))), f32x2 channel pairs.
    // OOB halo positions MUST stay 0 (edges is zero-padded for the gradient convs).
    for (int i = tid; i < 34 * 34; i += NTHREADS) {
        int r = i / 34, c = i % 34;
        int gy = y0 - 1 + r, gx = x0 - 1 + c;
        float ed = 0.f;
        if (gy >= 0 && gy < H && gx >= 0 && gx < W) {
            ull e1p[4] = {0ull, 0ull, 0ull, 0ull};
#pragma unroll
            for (int t = 0; t < 9; ++t) {
                float v = s_img[(r + t / 3) * 36 + c + t % 3];
                ull vv = pack2(v, v);
                fma2(e1p[0], vv, s_dw2[t * 4 + 0]);
                fma2(e1p[1], vv, s_dw2[t * 4 + 1]);
                fma2(e1p[2], vv, s_dw2[t * 4 + 2]);
                fma2(e1p[3], vv, s_dw2[t * 4 + 3]);
            }
            ull e2p[4] = {0ull, 0ull, 0ull, 0ull};
#pragma unroll
            for (int j = 0; j < 4; ++j) {
                float2 e = unpack2(e1p[j]);
                ull sa = pack2(e.x, e.x);
                ull sb = pack2(e.y, e.y);
                const int ca = (2 * j) * 4, cb = (2 * j + 1) * 4;
                fma2(e2p[0], sa, s_pw2[ca + 0]);
                fma2(e2p[1], sa, s_pw2[ca + 1]);
                fma2(e2p[2], sa, s_pw2[ca + 2]);
                fma2(e2p[3], sa, s_pw2[ca + 3]);
                fma2(e2p[0], sb, s_pw2[cb + 0]);
                fma2(e2p[1], sb, s_pw2[cb + 1]);
                fma2(e2p[2], sb, s_pw2[cb + 2]);
                fma2(e2p[3], sb, s_pw2[cb + 3]);
            }
            float s = 0.f;
#pragma unroll
            for (int k = 0; k < 4; ++k) {
                float2 rr = unpack2(e2p[k]);
                s += fmaxf(rr.x, 0.f) + fmaxf(rr.y, 0.f);
            }
            ed = __fdividef(s, 1.f + fabsf(s));
        }
        s_e[i] = ed;
    }
    __syncthreads();
    for (int i = tid; i < 26 * 34; i += NTHREADS)
        s_e2[i] = pack2(s_e[i], s_e[i + 8 * 34]);
    __syncthreads();

    const int tx = tid & 31, ty = tid >> 5;

    // gradient convs: 32 out channels, f32x2 lanes = pixel pairs (py, py+8)
    ull tap2[2][9];
#pragma unroll
    for (int pair = 0; pair < 2; ++pair)
#pragma unroll
        for (int t = 0; t < 9; ++t)
            tap2[pair][t] = s_e2[(ty + 16 * pair + t / 3) * 34 + tx + t % 3];

    float gxa[4] = {0.f, 0.f, 0.f, 0.f};
    float gya[4] = {0.f, 0.f, 0.f, 0.f};
#pragma unroll 1
    for (int co = 0; co < 32; ++co) {
        ull wx9[9], wy9[9];
#pragma unroll
        for (int t = 0; t < 9; ++t) {
            wx9[t] = s_wx2[t * 32 + co];
            wy9[t] = s_wy2[t * 32 + co];
        }
#pragma unroll
        for (int pair = 0; pair < 2; ++pair) {
            ull ax = 0ull, ay = 0ull;
#pragma unroll
            for (int t = 0; t < 9; ++t) {
                fma2(ax, tap2[pair][t], wx9[t]);
                fma2(ay, tap2[pair][t], wy9[t]);
            }
            float2 rx = unpack2(ax);
            float2 ry = unpack2(ay);
            gxa[2 * pair]     += fmaxf(rx.x, 0.f);
            gxa[2 * pair + 1] += fmaxf(rx.y, 0.f);
            gya[2 * pair]     += fmaxf(ry.x, 0.f);
            gya[2 * pair + 1] += fmaxf(ry.y, 0.f);
        }
    }

#pragma unroll
    for (int k = 0; k < 4; ++k) {
        // k=0 -> ty, k=1 -> ty+8, k=2 -> ty+16, k=3 -> ty+24 (matches gxa lane order)
        const int py = ty + 8 * (k & 1) + 16 * (k >> 1);
        const int ec = (py + 1) * 34 + tx + 1;
        float uc = s_u[ec];
        float xp = uc - s_u[ec - 1];
        float xn = s_u[ec + 1] - uc;
        float yn = s_u[ec - 34] - uc;
        float yp = uc - s_u[ec + 34];

        float kp = 0.f;
#pragma unroll
        for (int t = 0; t < 25; ++t)
            kp = fmaf(s_kp[(py + t / 5) * 36 + tx + t % 5], s_ws[t], kp);

        float gx = gxa[k], gy = gya[k];
        float fxp = fmaxf(gx, 0.f), fxn = fminf(gx, 0.f);
        float fyp = fmaxf(gy, 0.f), fyn = fminf(gy, 0.f);

        float r = uc + fxp * xp + fxn * xn + fyp * yp + fyn * yn + s_e[ec] + kp;
        out[((b * H) + (y0 + py)) * W + (x0 + tx)] = r;
    }
}

// ---------------- launch ----------------
extern "C" void kernel_launch(void* const* d_in, const int* in_sizes, int n_in,
                              void* d_out, int out_size) {
    (void)in_sizes; (void)n_in; (void)out_size;
    const float* u     = (const float*)d_in[0];
    const float* image = (const float*)d_in[1];
    const float* wx    = (const float*)d_in[2];
    const float* wy    = (const float*)d_in[3];
    const float* dw    = (const float*)d_in[4];
    const float* pw    = (const float*)d_in[5];
    const float* k0    = (const float*)d_in[6];
    const float* k1    = (const float*)d_in[7];
    const float* k2    = (const float*)d_in[8];
    const float* ws    = (const float*)d_in[9];
    const float* kap   = (const float*)d_in[10];
    float* out = (float*)d_out;

    dim3 gridF(W / TS, H / TS, B);
    dim3 gridS(32, B);

    k_compose<<<1, 648>>>(k0, k1, k2);
    k_kpre<<<gridF, dim3(128)>>>(u, kap);     // composed 11x11 conv everywhere
    k_c0s<<<gridS, dim3(NTHREADS)>>>(u, k0);  // staged c0: dist<=5 band
    k_c1s<<<gridS, dim3(128)>>>(k1);          // staged c1: dist<=3 band, pixel-pair
    k_c2ks<<<gridS, dim3(NTHREADS)>>>(kap);   // staged kpre overwrite: dist<=2 band
    k_final<<<gridF, dim3(NTHREADS)>>>(u, image, wx, wy, dw, pw, ws, out);
}

// round 6
// speedup vs baseline: 3.8054x; 1.0849x over previous
#include <cuda_runtime.h>
#include <cstdint>

typedef unsigned long long ull;

#define B 8
#define H 512
#define W 512
#define TS 32
#define NTHREADS 256

// ---------------- device scratch (allocation-free) ----------------
__device__ float g_kpre[B * H * W];
__device__ float g_k2s[72];
__device__ float g_kc[121];

// ---------------- f32x2 packed helpers (sm_100+) ----------------
__device__ __forceinline__ ull pack2(float lo, float hi) {
    ull r;
    asm("mov.b64 %0, {%1, %2};" : "=l"(r) : "f"(lo), "f"(hi));
    return r;
}
__device__ __forceinline__ float2 unpack2(ull v) {
    float2 r;
    asm("mov.b64 {%0, %1}, %2;" : "=f"(r.x), "=f"(r.y) : "l"(v));
    return r;
}
__device__ __forceinline__ void fma2(ull& acc, ull a, ull b) {
    asm("fma.rn.f32x2 %0, %1, %2, %0;" : "+l"(acc) : "l"(a), "l"(b));
}

// ---------------- border band decode: 32 blocks/batch, 64-px segments, bw=3 ----------------
__device__ __forceinline__ void band_region(int id, int bw,
                                            int& oy0, int& ox0, int& oR, int& oC) {
    int seg = id >> 3, s = id & 7;
    if (seg == 0)      { oy0 = 0;      ox0 = 64 * s; oR = bw; oC = 64; }
    else if (seg == 1) { oy0 = H - bw; ox0 = 64 * s; oR = bw; oC = 64; }
    else if (seg == 2) { oy0 = 64 * s; ox0 = 0;      oR = 64; oC = bw; }
    else               { oy0 = 64 * s; ox0 = W - bw; oR = 64; oC = bw; }
}

// ---------------- kernel: compose k0(5x5,1->8) o k1(5x5,8->8) o sum16(k2)(3x3,8->1) -> 11x11 ----------------
__global__ void k_compose(const float* __restrict__ k0,
                          const float* __restrict__ k1,
                          const float* __restrict__ k2) {
    __shared__ float s_k2s[72];
    __shared__ float s_K01[648]; // [ry(9)][rx(9)][c2(8)]
    const int tid = threadIdx.x;

    if (tid < 72) {
        float s = 0.f;
#pragma unroll
        for (int o = 0; o < 16; ++o) s += k2[tid * 16 + o];
        s_k2s[tid] = s;
        g_k2s[tid] = s;
    }
    __syncthreads();

    if (tid < 648) {
        int c2 = tid & 7;
        int rx = (tid >> 3) % 9;
        int ry = tid / 72;
        float v = 0.f;
        int sy0 = ry - 4 > 0 ? ry - 4 : 0, sy1 = ry < 4 ? ry : 4;
        int sx0 = rx - 4 > 0 ? rx - 4 : 0, sx1 = rx < 4 ? rx : 4;
        for (int sy = sy0; sy <= sy1; ++sy)
            for (int sx = sx0; sx <= sx1; ++sx) {
                int ty = ry - sy, txx = rx - sx;
                for (int c1 = 0; c1 < 8; ++c1)
                    v += k0[(sy * 5 + sx) * 8 + c1] *
                         k1[((ty * 5 + txx) * 8 + c1) * 8 + c2];
            }
        s_K01[(ry * 9 + rx) * 8 + c2] = v;
    }
    __syncthreads();

    if (tid < 121) {
        int fx = tid % 11, fy = tid / 11;
        float v = 0.f;
        int ry0 = fy - 2 > 0 ? fy - 2 : 0, ry1 = fy < 8 ? fy : 8;
        int rx0 = fx - 2 > 0 ? fx - 2 : 0, rx1 = fx < 8 ? fx : 8;
        for (int ry = ry0; ry <= ry1; ++ry)
            for (int rx = rx0; rx <= rx1; ++rx) {
                int vy = fy - ry, vx = fx - rx;
                for (int c2 = 0; c2 < 8; ++c2)
                    v += s_K01[(ry * 9 + rx) * 8 + c2] *
                         s_k2s[(vy * 3 + vx) * 8 + c2];
            }
        g_kc[tid] = v;
    }
}

// ---------------- kernel: kpre = conv11x11(u, g_kc) * kappa_kernel (register-sliding f32x2) ----------------
__global__ void k_kpre(const float* __restrict__ u, const float* __restrict__ kap) {
    __shared__ __align__(16) float s_t[42 * 42];
    __shared__ __align__(16) ull   s_K2[121];

    const int b = blockIdx.z;
    const int x0 = blockIdx.x * TS, y0 = blockIdx.y * TS;
    const int tid = threadIdx.x;

    for (int i = tid; i < 121; i += 128) {
        float w = g_kc[i];
        s_K2[i] = pack2(w, w);
    }
    for (int i = tid; i < 42 * 42; i += 128) {
        int r = i / 42, c = i % 42;
        int gy = y0 - 5 + r, gx = x0 - 5 + c;
        float v = 0.f;
        if (gy >= 0 && gy < H && gx >= 0 && gx < W)
            v = u[((b * H) + gy) * W + gx];
        s_t[i] = v;
    }
    __syncthreads();

    const int tx = tid & 31, ty = tid >> 5;
    const int r0 = ty * 8;

    ull acc[4] = {0ull, 0ull, 0ull, 0ull};

#pragma unroll 1
    for (int dx = 0; dx < 11; ++dx) {
        float t[18];
        const float* col = s_t + r0 * 42 + tx + dx;
#pragma unroll
        for (int i = 0; i < 18; ++i) t[i] = col[i * 42];
        ull pk[17];
#pragma unroll
        for (int i = 0; i < 17; ++i) pk[i] = pack2(t[i], t[i + 1]);
#pragma unroll
        for (int dy = 0; dy < 11; ++dy) {
            ull w = s_K2[dy * 11 + dx];
            fma2(acc[0], pk[dy],     w);
            fma2(acc[1], pk[dy + 2], w);
            fma2(acc[2], pk[dy + 4], w);
            fma2(acc[3], pk[dy + 6], w);
        }
    }

    const int x = x0 + tx;
#pragma unroll
    for (int p = 0; p < 4; ++p) {
        float2 r = unpack2(acc[p]);
        int y = y0 + r0 + 2 * p;
        g_kpre[((b * H) + y) * W + x]     = r.x * kap[y * W + x];
        g_kpre[((b * H) + y + 1) * W + x] = r.y * kap[(y + 1) * W + x];
    }
}

// ---------------- fused band kernel: u -> c0 -> c1 -> c2k*kap entirely in smem (band 3) ----------------
// Staged-exact overwrite of the composed conv in the dist<=2 border band.
__global__ void k_band(const float* __restrict__ u,
                       const float* __restrict__ k0,
                       const float* __restrict__ k1,
                       const float* __restrict__ kap) {
    __shared__ __align__(16) float s_u[962];       // (oR+10)*(oC+10) = 13*74 or 74*13
    __shared__ __align__(16) ull   s_w0[100];      // k0 channel pairs
    __shared__ __align__(16) float s_w1[1600];     // k1 raw
    __shared__ float s_k2[72];
    __shared__ __align__(16) float s_c0[8 * 630];  // planar [ci][(oR+6)*(oC+6)]
    __shared__ __align__(16) float s_c1[8 * 330];  // planar [ci][(oR+2)*(oC+2)]

    const int b = blockIdx.y;
    int oy0, ox0, oR, oC;
    band_region(blockIdx.x, 3, oy0, ox0, oR, oC);
    const int RWu = oC + 10;
    const int RW0 = oC + 6;
    const int RW1 = oC + 2;
    const int Nu = (oR + 10) * RWu;  // 962
    const int N0 = (oR + 6) * RW0;   // 630
    const int N1 = (oR + 2) * RW1;   // 330
    const int tid = threadIdx.x;

    for (int i = tid; i < 100; i += NTHREADS) {
        float2 w = ((const float2*)k0)[i];
        s_w0[i] = pack2(w.x, w.y);
    }
    for (int i = tid; i < 1600; i += NTHREADS) s_w1[i] = k1[i];
    for (int i = tid; i < 72; i += NTHREADS) s_k2[i] = g_k2s[i];
    for (int i = tid; i < Nu; i += NTHREADS) {
        int r = i / RWu, c = i % RWu;
        int gy = oy0 - 5 + r, gx = ox0 - 5 + c;
        float v = 0.f;
        if (gy >= 0 && gy < H && gx >= 0 && gx < W)
            v = u[((b * H) + gy) * W + gx];
        s_u[i] = v;
    }
    __syncthreads();

    // phase 2: c0 = conv5x5 1->8 on the (oR+6)x(oC+6) region (0 outside image)
    for (int i = tid; i < N0; i += NTHREADS) {
        int r = i / RW0, c = i % RW0;
        int gy = oy0 - 3 + r, gx = ox0 - 3 + c;
        ull acc[4] = {0ull, 0ull, 0ull, 0ull};
        if (gy >= 0 && gy < H && gx >= 0 && gx < W) {
#pragma unroll
            for (int t = 0; t < 25; ++t) {
                int dy = t / 5, dx = t % 5;
                float v = s_u[(r + dy) * RWu + c + dx];
                ull vv = pack2(v, v);
                fma2(acc[0], vv, s_w0[t * 4 + 0]);
                fma2(acc[1], vv, s_w0[t * 4 + 1]);
                fma2(acc[2], vv, s_w0[t * 4 + 2]);
                fma2(acc[3], vv, s_w0[t * 4 + 3]);
            }
        }
        float2 a0 = unpack2(acc[0]);
        float2 a1 = unpack2(acc[1]);
        float2 a2 = unpack2(acc[2]);
        float2 a3 = unpack2(acc[3]);
        s_c0[0 * 630 + i] = a0.x;  s_c0[1 * 630 + i] = a0.y;
        s_c0[2 * 630 + i] = a1.x;  s_c0[3 * 630 + i] = a1.y;
        s_c0[4 * 630 + i] = a2.x;  s_c0[5 * 630 + i] = a2.y;
        s_c0[6 * 630 + i] = a3.x;  s_c0[7 * 630 + i] = a3.y;
    }
    __syncthreads();

    // phase 3: c1 = conv5x5 8->8 on the (oR+2)x(oC+2) region (0 outside image)
    for (int i = tid; i < N1; i += NTHREADS) {
        int r = i / RW1, c = i % RW1;
        int gy = oy0 - 1 + r, gx = ox0 - 1 + c;
        ull acc[4] = {0ull, 0ull, 0ull, 0ull};
        if (gy >= 0 && gy < H && gx >= 0 && gx < W) {
#pragma unroll 1
            for (int t = 0; t < 25; ++t) {
                int dy = t / 5, dx = t % 5;
                const float* wp = s_w1 + t * 64;
                const int base = (r + dy) * RW0 + c + dx;
#pragma unroll
                for (int ci = 0; ci < 8; ++ci) {
                    ulonglong2 wA = *(const ulonglong2*)(wp + ci * 8);
                    ulonglong2 wB = *(const ulonglong2*)(wp + ci * 8 + 4);
                    float v = s_c0[ci * 630 + base];
                    ull p = pack2(v, v);
                    fma2(acc[0], p, wA.x); fma2(acc[1], p, wA.y);
                    fma2(acc[2], p, wB.x); fma2(acc[3], p, wB.y);
                }
            }
        }
        float2 a0 = unpack2(acc[0]);
        float2 a1 = unpack2(acc[1]);
        float2 a2 = unpack2(acc[2]);
        float2 a3 = unpack2(acc[3]);
        s_c1[0 * 330 + i] = a0.x;  s_c1[1 * 330 + i] = a0.y;
        s_c1[2 * 330 + i] = a1.x;  s_c1[3 * 330 + i] = a1.y;
        s_c1[4 * 330 + i] = a2.x;  s_c1[5 * 330 + i] = a2.y;
        s_c1[6 * 330 + i] = a3.x;  s_c1[7 * 330 + i] = a3.y;
    }
    __syncthreads();

    // phase 4: kpre = conv3x3(c1, k2s) * kap on the oR x oC output band
    for (int i = tid; i < oR * oC; i += NTHREADS) {
        int r = i / oC, c = i % oC;
        float acc = 0.f;
#pragma unroll
        for (int t = 0; t < 9; ++t) {
            int dy = t / 3, dx = t % 3;
            const int idx = (r + dy) * RW1 + c + dx;
#pragma unroll
            for (int ci = 0; ci < 8; ++ci)
                acc = fmaf(s_c1[ci * 330 + idx], s_k2[t * 8 + ci], acc);
        }
        int y = oy0 + r, x = ox0 + c;
        g_kpre[((b * H) + y) * W + x] = acc * kap[y * W + x];
    }
}

// ---------------- final fused kernel: edges in-tile f32x2 (OOB-masked), grads (LDS.128 co-pairs), diffs, smoother, sum ----------------
__global__ void k_final(const float* __restrict__ u,
                        const float* __restrict__ image,
                        const float* __restrict__ wx,  // (3,3,1,32) -> [t*32+co]
                        const float* __restrict__ wy,
                        const float* __restrict__ dw,  // (3,3,1,8)
                        const float* __restrict__ pw,  // (1,1,8,8)
                        const float* __restrict__ ws,  // (5,5,1,1)
                        float* __restrict__ out) {
    __shared__ __align__(16) float s_img[36 * 36];
    __shared__ __align__(16) float s_e[34 * 34];
    __shared__ __align__(16) ull   s_e2[26 * 34];
    __shared__ __align__(16) float s_u[34 * 34];
    __shared__ __align__(16) float s_kp[36 * 36];
    __shared__ __align__(16) ull   s_wx2[288];
    __shared__ __align__(16) ull   s_wy2[288];
    __shared__ __align__(16) ull   s_dw2[36];  // dw channel pairs
    __shared__ __align__(16) ull   s_pw2[32];  // pw co pairs
    __shared__ float s_ws[25];

    const int b = blockIdx.z;
    const int x0 = blockIdx.x * TS, y0 = blockIdx.y * TS;
    const int tid = threadIdx.x;

    for (int i = tid; i < 288; i += NTHREADS) {
        float a = wx[i], c = wy[i];
        s_wx2[i] = pack2(a, a);
        s_wy2[i] = pack2(c, c);
    }
    if (tid < 36) {
        float2 v = ((const float2*)dw)[tid];
        s_dw2[tid] = pack2(v.x, v.y);
    }
    if (tid >= 64 && tid < 96) {
        float2 v = ((const float2*)pw)[tid - 64];
        s_pw2[tid - 64] = pack2(v.x, v.y);
    }
    if (tid >= 128 && tid < 153) s_ws[tid - 128] = ws[tid - 128];
    for (int i = tid; i < 36 * 36; i += NTHREADS) {
        int r = i / 36, c = i % 36;
        int gy = y0 - 2 + r, gx = x0 - 2 + c;
        float vi = 0.f, vk = 0.f;
        if (gy >= 0 && gy < H && gx >= 0 && gx < W) {
            int idx = ((b * H) + gy) * W + gx;
            vi = image[idx];
            vk = g_kpre[idx];
        }
        s_img[i] = vi;
        s_kp[i] = vk;
    }
    for (int i = tid; i < 34 * 34; i += NTHREADS) {
        int r = i / 34, c = i % 34;
        int gy = y0 - 1 + r, gx = x0 - 1 + c;
        float v = 0.f;
        if (gy >= 0 && gy < H && gx >= 0 && gx < W)
            v = u[((b * H) + gy) * W + gx];
        s_u[i] = v;
    }
    __syncthreads();

    // edges = softsign(sum_co relu(pw(dw(image)))), f32x2 channel pairs.
    // OOB halo positions MUST stay 0 (edges is zero-padded for the gradient convs).
    for (int i = tid; i < 34 * 34; i += NTHREADS) {
        int r = i / 34, c = i % 34;
        int gy = y0 - 1 + r, gx = x0 - 1 + c;
        float ed = 0.f;
        if (gy >= 0 && gy < H && gx >= 0 && gx < W) {
            ull e1p[4] = {0ull, 0ull, 0ull, 0ull};
#pragma unroll
            for (int t = 0; t < 9; ++t) {
                float v = s_img[(r + t / 3) * 36 + c + t % 3];
                ull vv = pack2(v, v);
                fma2(e1p[0], vv, s_dw2[t * 4 + 0]);
                fma2(e1p[1], vv, s_dw2[t * 4 + 1]);
                fma2(e1p[2], vv, s_dw2[t * 4 + 2]);
                fma2(e1p[3], vv, s_dw2[t * 4 + 3]);
            }
            ull e2p[4] = {0ull, 0ull, 0ull, 0ull};
#pragma unroll
            for (int j = 0; j < 4; ++j) {
                float2 e = unpack2(e1p[j]);
                ull sa = pack2(e.x, e.x);
                ull sb = pack2(e.y, e.y);
                const int ca = (2 * j) * 4, cb = (2 * j + 1) * 4;
                fma2(e2p[0], sa, s_pw2[ca + 0]);
                fma2(e2p[1], sa, s_pw2[ca + 1]);
                fma2(e2p[2], sa, s_pw2[ca + 2]);
                fma2(e2p[3], sa, s_pw2[ca + 3]);
                fma2(e2p[0], sb, s_pw2[cb + 0]);
                fma2(e2p[1], sb, s_pw2[cb + 1]);
                fma2(e2p[2], sb, s_pw2[cb + 2]);
                fma2(e2p[3], sb, s_pw2[cb + 3]);
            }
            float s = 0.f;
#pragma unroll
            for (int k = 0; k < 4; ++k) {
                float2 rr = unpack2(e2p[k]);
                s += fmaxf(rr.x, 0.f) + fmaxf(rr.y, 0.f);
            }
            ed = __fdividef(s, 1.f + fabsf(s));
        }
        s_e[i] = ed;
    }
    __syncthreads();
    for (int i = tid; i < 26 * 34; i += NTHREADS)
        s_e2[i] = pack2(s_e[i], s_e[i + 8 * 34]);
    __syncthreads();

    const int tx = tid & 31, ty = tid >> 5;

    // gradient convs: 32 out channels, f32x2 lanes = pixel pairs (py, py+8),
    // co processed in pairs with LDS.128 weight loads (halves smem traffic).
    ull tap2[2][9];
#pragma unroll
    for (int pair = 0; pair < 2; ++pair)
#pragma unroll
        for (int t = 0; t < 9; ++t)
            tap2[pair][t] = s_e2[(ty + 16 * pair + t / 3) * 34 + tx + t % 3];

    float gxa[4] = {0.f, 0.f, 0.f, 0.f};
    float gya[4] = {0.f, 0.f, 0.f, 0.f};
#pragma unroll 1
    for (int co = 0; co < 32; co += 2) {
        ull ax[2][2] = {{0ull, 0ull}, {0ull, 0ull}};  // [pair][co01]
        ull ay[2][2] = {{0ull, 0ull}, {0ull, 0ull}};
#pragma unroll
        for (int t = 0; t < 9; ++t) {
            ulonglong2 wxp = *(const ulonglong2*)(s_wx2 + t * 32 + co);
            ulonglong2 wyp = *(const ulonglong2*)(s_wy2 + t * 32 + co);
            fma2(ax[0][0], tap2[0][t], wxp.x); fma2(ax[0][1], tap2[0][t], wxp.y);
            fma2(ax[1][0], tap2[1][t], wxp.x); fma2(ax[1][1], tap2[1][t], wxp.y);
            fma2(ay[0][0], tap2[0][t], wyp.x); fma2(ay[0][1], tap2[0][t], wyp.y);
            fma2(ay[1][0], tap2[1][t], wyp.x); fma2(ay[1][1], tap2[1][t], wyp.y);
        }
#pragma unroll
        for (int pair = 0; pair < 2; ++pair) {
#pragma unroll
            for (int j = 0; j < 2; ++j) {
                float2 rx = unpack2(ax[pair][j]);
                float2 ry = unpack2(ay[pair][j]);
                gxa[2 * pair]     += fmaxf(rx.x, 0.f);
                gxa[2 * pair + 1] += fmaxf(rx.y, 0.f);
                gya[2 * pair]     += fmaxf(ry.x, 0.f);
                gya[2 * pair + 1] += fmaxf(ry.y, 0.f);
            }
        }
    }

#pragma unroll
    for (int k = 0; k < 4; ++k) {
        // k=0 -> ty, k=1 -> ty+8, k=2 -> ty+16, k=3 -> ty+24 (matches gxa lane order)
        const int py = ty + 8 * (k & 1) + 16 * (k >> 1);
        const int ec = (py + 1) * 34 + tx + 1;
        float uc = s_u[ec];
        float xp = uc - s_u[ec - 1];
        float xn = s_u[ec + 1] - uc;
        float yn = s_u[ec - 34] - uc;
        float yp = uc - s_u[ec + 34];

        float kp = 0.f;
#pragma unroll
        for (int t = 0; t < 25; ++t)
            kp = fmaf(s_kp[(py + t / 5) * 36 + tx + t % 5], s_ws[t], kp);

        float gx = gxa[k], gy = gya[k];
        float fxp = fmaxf(gx, 0.f), fxn = fminf(gx, 0.f);
        float fyp = fmaxf(gy, 0.f), fyn = fminf(gy, 0.f);

        float r = uc + fxp * xp + fxn * xn + fyp * yp + fyn * yn + s_e[ec] + kp;
        out[((b * H) + (y0 + py)) * W + (x0 + tx)] = r;
    }
}

// ---------------- launch ----------------
extern "C" void kernel_launch(void* const* d_in, const int* in_sizes, int n_in,
                              void* d_out, int out_size) {
    (void)in_sizes; (void)n_in; (void)out_size;
    const float* u     = (const float*)d_in[0];
    const float* image = (const float*)d_in[1];
    const float* wx    = (const float*)d_in[2];
    const float* wy    = (const float*)d_in[3];
    const float* dw    = (const float*)d_in[4];
    const float* pw    = (const float*)d_in[5];
    const float* k0    = (const float*)d_in[6];
    const float* k1    = (const float*)d_in[7];
    const float* k2    = (const float*)d_in[8];
    const float* ws    = (const float*)d_in[9];
    const float* kap   = (const float*)d_in[10];
    float* out = (float*)d_out;

    dim3 gridF(W / TS, H / TS, B);

    k_compose<<<1, 648>>>(k0, k1, k2);
    k_kpre<<<gridF, dim3(128)>>>(u, kap);            // composed 11x11 conv everywhere
    k_band<<<dim3(32, B), dim3(NTHREADS)>>>(u, k0, k1, kap);  // staged-exact band overwrite (fused)
    k_final<<<gridF, dim3(NTHREADS)>>>(u, image, wx, wy, dw, pw, ws, out);
}